// round 14
// baseline (speedup 1.0000x reference)
#include <cuda_runtime.h>
#include <cuda.h>
#include <cuda_fp16.h>
#include <math.h>
#include <stdint.h>

#define SP 65536        /* 16^4 */
#define CIN 32
#define H 128
#define COUT 32
#define SED 8

// ---------------- scratch (device globals) ----------------
__device__ __align__(1024) __half g_h1h[SP * H];     // gelu1 out [v][c] fp16 (conv2 TMA src)
__device__ __align__(1024) __half g_w2h[81 * H * H]; // conv2 weights fp16 [tap][o][c]
__device__ __half g_h2[H * SP];                      // conv2 out fp16 [o][v]
__device__ float g_part0[512 * 2];
__device__ float g_part1[512 * 2];
__device__ float g_part2[256 * 2];
__device__ float g_part3[256 * 2];
__device__ float g_chsump[256 * 128];                // SE partials [blk][c]
__device__ unsigned g_cnt[8];                        // last_block counters (kernel-scope)
__device__ unsigned g_gA[4], g_gB[4], g_gR[4];       // grid gates (self-resetting)
__device__ float g_w1eff[H * CIN];
__device__ float g_bias1[H];
__device__ float g_a1[H], g_b1[H], g_a2[H], g_b2[H], g_a3[COUT], g_b3[COUT];
__device__ __half g_w3h[COUT * H];                   // SE-folded conv3 weights fp16 [o][c]

// ---------------- PTX helpers (plain sm_90/sm_80 features only) ----------------
__device__ __forceinline__ uint32_t smem_u32(const void* p) {
    uint32_t a;
    asm("{ .reg .u64 t; cvta.to.shared.u64 t, %1; cvt.u32.u64 %0, t; }" : "=r"(a) : "l"(p));
    return a;
}

#define MBARRIER_INIT(mbar, cnt) \
    asm volatile("mbarrier.init.shared.b64 [%0], %1;" :: "r"((uint32_t)(mbar)), "r"((uint32_t)(cnt)) : "memory")

#define MBARRIER_EXPECT_TX(mbar, bytes) \
    asm volatile("mbarrier.arrive.expect_tx.shared.b64 _, [%0], %1;" :: "r"((uint32_t)(mbar)), "r"((uint32_t)(bytes)) : "memory")

#define MBARRIER_ARRIVE(mbar) \
    asm volatile("mbarrier.arrive.shared.b64 _, [%0];" :: "r"((uint32_t)(mbar)) : "memory")

#define MBARRIER_WAIT_PARITY(mbar, ph) do { \
    uint32_t _m = (uint32_t)(mbar); uint32_t _p = (uint32_t)(ph); uint32_t _d; \
    asm volatile("{\n\t.reg .pred p;\n\t" \
        "mbarrier.try_wait.parity.acquire.cta.shared::cta.b64 p, [%1], %2;\n\t" \
        "selp.b32 %0, 1, 0, p;\n\t}" : "=r"(_d) : "r"(_m), "r"(_p) : "memory"); \
    if (!_d) { \
        asm volatile("{\n\t.reg .pred P1;\n\t" \
            "WL_%=:\n\t" \
            "mbarrier.try_wait.parity.acquire.cta.shared::cta.b64 P1, [%0], %1, 0x989680;\n\t" \
            "@P1 bra.uni WD_%=;\n\t" \
            "bra.uni WL_%=;\n\t" \
            "WD_%=:\n\t}" :: "r"(_m), "r"(_p) : "memory"); \
    } \
} while (0)

#define TMA_LOAD_3D(smem, map, c0, c1, c2, mbar) \
    asm volatile("cp.async.bulk.tensor.3d.shared::cta.global.tile.mbarrier::complete_tx::bytes " \
                 "[%0], [%1, {%2, %3, %4}], [%5];" \
                 :: "r"((uint32_t)(smem)), "l"(map), "r"((int)(c0)), "r"((int)(c1)), "r"((int)(c2)), \
                    "r"((uint32_t)(mbar)) : "memory")

#define TMA_LOAD_5D(smem, map, c0, c1, c2, c3, c4, mbar) \
    asm volatile("cp.async.bulk.tensor.5d.shared::cta.global.tile.mbarrier::complete_tx::bytes " \
                 "[%0], [%1, {%2, %3, %4, %5, %6}], [%7];" \
                 :: "r"((uint32_t)(smem)), "l"(map), "r"((int)(c0)), "r"((int)(c1)), "r"((int)(c2)), \
                    "r"((int)(c3)), "r"((int)(c4)), "r"((uint32_t)(mbar)) : "memory")

__device__ __forceinline__ void ldsm4(uint32_t* r, uint32_t addr) {
    asm volatile("ldmatrix.sync.aligned.m8n8.x4.shared.b16 {%0,%1,%2,%3}, [%4];"
                 : "=r"(r[0]), "=r"(r[1]), "=r"(r[2]), "=r"(r[3]) : "r"(addr));
}

__device__ __forceinline__ void mma16816(float* d, const uint32_t* a, const uint32_t* b) {
    asm volatile("mma.sync.aligned.m16n8k16.row.col.f32.f16.f16.f32 "
                 "{%0,%1,%2,%3}, {%4,%5,%6,%7}, {%8,%9}, {%0,%1,%2,%3};"
                 : "+f"(d[0]), "+f"(d[1]), "+f"(d[2]), "+f"(d[3])
                 : "r"(a[0]), "r"(a[1]), "r"(a[2]), "r"(a[3]), "r"(b[0]), "r"(b[1]));
}

__device__ __forceinline__ float geluf(float v) {
    return 0.5f * v * (1.0f + erff(v * 0.70710678118654752f));
}

#define SWZ(off) ((off) ^ (((off) >> 3) & 0x70))

__device__ __forceinline__ void reduce2_part(float s, float q, float* dst) {
    __shared__ float rA[32], rB[32];
    const unsigned full = 0xffffffffu;
#pragma unroll
    for (int off = 16; off > 0; off >>= 1) {
        s += __shfl_down_sync(full, s, off);
        q += __shfl_down_sync(full, q, off);
    }
    int lane = threadIdx.x & 31, wid = threadIdx.x >> 5;
    int nw = (blockDim.x + 31) >> 5;
    if (lane == 0) { rA[wid] = s; rB[wid] = q; }
    __syncthreads();
    if (threadIdx.x == 0) {
        float S = 0.f, Q = 0.f;
        for (int w = 0; w < nw; w++) { S += rA[w]; Q += rB[w]; }
        dst[0] = S; dst[1] = Q;
    }
}

__device__ __forceinline__ bool last_block(int idx, unsigned n) {
    __shared__ unsigned lb_done;
    __threadfence();
    if (threadIdx.x == 0) {
        unsigned old = atomicAdd(&g_cnt[idx], 1u);
        lb_done = (old == n - 1) ? 1u : 0u;
        if (lb_done) g_cnt[idx] = 0;
    }
    __syncthreads();
    if (lb_done) __threadfence();
    return lb_done != 0;
}

__device__ __forceinline__ void finalize_stats(const float* part, int n, double invN,
                                               float& mu, float& inv) {
    __shared__ float rA[32], rB[32], bc2[2];
    float s = 0.f, q = 0.f;
    for (int i = threadIdx.x; i < n; i += blockDim.x) {
        s += part[2 * i];
        q += part[2 * i + 1];
    }
    const unsigned full = 0xffffffffu;
#pragma unroll
    for (int off = 16; off > 0; off >>= 1) {
        s += __shfl_down_sync(full, s, off);
        q += __shfl_down_sync(full, q, off);
    }
    int lane = threadIdx.x & 31, wid = threadIdx.x >> 5;
    int nw = (blockDim.x + 31) >> 5;
    if (lane == 0) { rA[wid] = s; rB[wid] = q; }
    __syncthreads();
    if (threadIdx.x == 0) {
        float S = 0.f, Q = 0.f;
        for (int w = 0; w < nw; w++) { S += rA[w]; Q += rB[w]; }
        bc2[0] = S; bc2[1] = Q;
    }
    __syncthreads();
    double m = (double)bc2[0] * invN;
    double var = (double)bc2[1] * invN - m * m;
    mu = (float)m;
    inv = (float)(1.0 / sqrt(var + 1e-5));
}

// ---------------- grid gate (all blocks resident; self-resetting) ----------------
__device__ __forceinline__ bool gate_arrive(int gi, unsigned n) {
    __shared__ unsigned lastf;
    __threadfence();
    if (threadIdx.x == 0)
        lastf = (atomicAdd(&g_gA[gi], 1u) == n - 1) ? 1u : 0u;
    __syncthreads();
    return lastf != 0;
}
__device__ __forceinline__ void gate_release(int gi) {
    __threadfence();
    if (threadIdx.x == 0) atomicExch(&g_gR[gi], 1u);
}
__device__ __forceinline__ void gate_wait(int gi, unsigned n) {
    if (threadIdx.x == 0) {
        while (atomicAdd(&g_gR[gi], 0u) == 0u) __nanosleep(64);
    }
    __syncthreads();
    __threadfence();
    if (threadIdx.x == 0) {
        if (atomicAdd(&g_gB[gi], 1u) == n - 1) {
            g_gA[gi] = 0u;
            g_gB[gi] = 0u;
            atomicExch(&g_gR[gi], 0u);
        }
    }
}

// ---------------- kernel 1: stats of x + w2 transpose ----------------
__global__ void __launch_bounds__(256) k_stats0wt2(const float* __restrict__ x,
                                                   const float* __restrict__ w2,
                                                   const float* __restrict__ w1,
                                                   const float* __restrict__ g0w,
                                                   const float* __restrict__ g0b) {
    int bid = blockIdx.x;
    int tid = threadIdx.x;
    if (bid >= 512) {
        __shared__ float swt[2592];
        int base_oc = (bid - 512) * 32;
        const float* wsrc = w2 + base_oc * 81;
        for (int idx = tid; idx < 2592; idx += 256) swt[idx] = wsrc[idx];
        __syncthreads();
        for (int idx = tid; idx < 2592; idx += 256) {
            int t = idx >> 5;
            int ol = idx & 31;
            g_w2h[t * 16384 + base_oc + ol] = __float2half(swt[ol * 81 + t]);
        }
        return;
    }
    float s = 0.f, q = 0.f;
    int base = bid * 4096 + tid;
#pragma unroll
    for (int k = 0; k < 16; k++) {
        float v = x[base + k * 256];
        s += v;
        q = fmaf(v, v, q);
    }
    reduce2_part(s, q, &g_part0[bid * 2]);
    if (last_block(0, 512)) {
        float mu0, inv0;
        finalize_stats(g_part0, 512, 1.0 / (double)(CIN * SP), mu0, inv0);
        if (tid < 128) {
            int o = tid;
            float bias = 0.f;
            for (int c = 0; c < CIN; c++) {
                float a = inv0 * g0w[c];
                float b = g0b[c] - mu0 * a;
                float w = w1[o * CIN + c];
                g_w1eff[o * CIN + c] = w * a;
                bias = fmaf(w, b, bias);
            }
            g_bias1[o] = bias;
        }
    }
}

// ---------------- kernel 2: FUSED conv1 + GN1 + GELU + transpose ----------------
// 512 blocks x 128 thr, ~50KB dyn smem -> 4/SM -> all 512 resident (gate-safe).
// Tile kept in smem across the gate; h1 never hits global.
#define C1_TILE 0
#define C1_W 32768
#define C1_AB 49152
#define C1_SMEM (C1_AB + 1024)

__global__ void __launch_bounds__(128) k_conv1g(const float* __restrict__ x,
                                                const float* __restrict__ gn1w,
                                                const float* __restrict__ gn1b) {
    extern __shared__ __align__(1024) char smem[];
    float* swf = (float*)(smem + C1_W);
    float* sab = (float*)(smem + C1_AB);
    __shared__ float sb[H];
    int tid = threadIdx.x;
    for (int i = tid; i < H * CIN; i += 128) swf[i] = g_w1eff[i];
    sb[tid] = g_bias1[tid];
    __syncthreads();
    int v = blockIdx.x * 128 + tid;
    float xr[CIN];
#pragma unroll
    for (int c = 0; c < CIN; c++) xr[c] = x[c * SP + v];
    float s = 0.f, q = 0.f;
    for (int o = 0; o < H; o++) {
        const float4* wr = (const float4*)(&swf[o * CIN]);
        float a0 = 0.f, a1 = 0.f, a2 = 0.f, a3 = 0.f;
#pragma unroll
        for (int g = 0; g < 2; g++) {
            float4 w0 = wr[g * 4 + 0], w1v = wr[g * 4 + 1], w2v = wr[g * 4 + 2], w3v = wr[g * 4 + 3];
            int b = g * 16;
            a0 = fmaf(w0.x, xr[b + 0], a0);  a0 = fmaf(w0.y, xr[b + 1], a0);
            a1 = fmaf(w0.z, xr[b + 2], a1);  a1 = fmaf(w0.w, xr[b + 3], a1);
            a0 = fmaf(w1v.x, xr[b + 4], a0); a0 = fmaf(w1v.y, xr[b + 5], a0);
            a1 = fmaf(w1v.z, xr[b + 6], a1); a1 = fmaf(w1v.w, xr[b + 7], a1);
            a2 = fmaf(w2v.x, xr[b + 8], a2); a2 = fmaf(w2v.y, xr[b + 9], a2);
            a3 = fmaf(w2v.z, xr[b + 10], a3); a3 = fmaf(w2v.w, xr[b + 11], a3);
            a2 = fmaf(w3v.x, xr[b + 12], a2); a2 = fmaf(w3v.y, xr[b + 13], a2);
            a3 = fmaf(w3v.z, xr[b + 14], a3); a3 = fmaf(w3v.w, xr[b + 15], a3);
        }
        float acc = sb[o] + (a0 + a1) + (a2 + a3);
        uint32_t off = (uint32_t)(tid * 256 + o * 2);
        *(__half*)(smem + SWZ(off)) = __float2half(acc);
        s += acc;
        q = fmaf(acc, acc, q);
    }
    reduce2_part(s, q, &g_part1[blockIdx.x * 2]);
    // ---- grid gate 0: GN1 coefficients ----
    if (gate_arrive(0, 512)) {
        float mu1, inv1;
        finalize_stats(g_part1, 512, 1.0 / (double)(H * SP), mu1, inv1);
        float a = gn1w[tid] * inv1;
        g_a1[tid] = a;
        g_b1[tid] = gn1b[tid] - mu1 * a;
        gate_release(0);
    }
    gate_wait(0, 512);
    sab[tid] = g_a1[tid];
    sab[128 + tid] = g_b1[tid];
    __syncthreads();
    // GELU + transposed write: thread owns row tid (128 halves = 16 uint4)
    uint4* dst = (uint4*)&g_h1h[(size_t)v * 128];
#pragma unroll
    for (int k = 0; k < 16; k++) {
        uint4 hv = *(uint4*)(smem + SWZ((uint32_t)(tid * 256 + k * 16)));
        uint32_t w[4] = {hv.x, hv.y, hv.z, hv.w};
        uint32_t r[4];
#pragma unroll
        for (int p = 0; p < 4; p++) {
            int c0 = k * 8 + p * 2;
            __half2 h2v = *(__half2*)&w[p];
            float f0 = geluf(fmaf(sab[c0], __half2float(h2v.x), sab[128 + c0]));
            float f1 = geluf(fmaf(sab[c0 + 1], __half2float(h2v.y), sab[128 + c0 + 1]));
            __half2 o2 = __floats2half2_rn(f0, f1);
            r[p] = *(uint32_t*)&o2;
        }
        dst[k] = make_uint4(r[0], r[1], r[2], r[3]);
    }
}

// ---------------- kernel 3: conv2 = TMA + ldmatrix + mma.sync (r12 verbatim) --------
#define NSTAGE 2
#define STAGE_BYTES 98304
#define SM_DATA 1024
#define SMEM_TOTAL (SM_DATA + NSTAGE * STAGE_BYTES)
#define TILE_TX 98304

__device__ __forceinline__ void issue_tile(uint32_t sb, int i, int xx, int yy,
                                           const CUtensorMap* tw, const CUtensorMap* tx) {
    int s = i & 1;
    uint32_t fullb = sb + s * 8;
    MBARRIER_EXPECT_TX(fullb, TILE_TX);
    int dx = i / 27;
    int r27 = i - dx * 27;
    int dy = r27 / 9;
    int r9 = r27 - dy * 9;
    int dz = r9 / 3;
    int dw = r9 - dz * 3;
    uint32_t D = sb + SM_DATA + s * STAGE_BYTES;
    TMA_LOAD_3D(D, tw, 0, 0, i, fullb);
    TMA_LOAD_3D(D + 16384, tw, 64, 0, i, fullb);
    TMA_LOAD_5D(D + 32768, tx, 0, dw - 1, dz - 1, yy + dy - 1, xx + dx - 1, fullb);
    TMA_LOAD_5D(D + 65536, tx, 64, dw - 1, dz - 1, yy + dy - 1, xx + dx - 1, fullb);
}

__global__ void __launch_bounds__(512, 1) k_conv2mma(const __grid_constant__ CUtensorMap tw,
                                                     const __grid_constant__ CUtensorMap tx,
                                                     const float* __restrict__ gn2w,
                                                     const float* __restrict__ gn2b) {
    extern __shared__ __align__(1024) char smem[];
    uint32_t sb = smem_u32(smem);
    int tid = threadIdx.x;
    int lane = tid & 31, wid = tid >> 5;
    int wm = wid & 3, wn = wid >> 2;
    int bx = blockIdx.x;
    int xx = bx >> 4, yy = bx & 15;

    if (tid == 0) {
        for (int s = 0; s < NSTAGE; s++) {
            MBARRIER_INIT(sb + s * 8, 1);
            MBARRIER_INIT(sb + 32 + s * 8, 16);
        }
    }
    __syncthreads();
    if (tid == 0) {
        issue_tile(sb, 0, xx, yy, &tw, &tx);
        issue_tile(sb, 1, xx, yy, &tw, &tx);
    }

    float acc[2][8][4];
#pragma unroll
    for (int a = 0; a < 2; a++)
#pragma unroll
        for (int b = 0; b < 8; b++)
#pragma unroll
            for (int cc = 0; cc < 4; cc++) acc[a][b][cc] = 0.f;

    const uint32_t swx = (lane & 7) << 4;
    const uint32_t aSel = lane >> 4;
    const uint32_t bSel = (lane >> 3) & 1;
    const int aRow = wm * 32 + (lane & 15);
    const int bRow = wn * 64 + (lane & 7) + ((lane >> 4) << 3);

    for (int i = 0; i < 81; i++) {
        int st = i & 1;
        int ph = (i >> 1) & 1;
        MBARRIER_WAIT_PARITY(sb + st * 8, ph);
        uint32_t D = sb + SM_DATA + st * STAGE_BYTES;
#pragma unroll
        for (int j = 0; j < 8; j++) {
            int half = j >> 2, jl = j & 3;
            uint32_t aB0 = D + half * 16384 + aRow * 128;
            uint32_t bB0 = D + 32768 + half * 32768 + bRow * 128;
            uint32_t ac = (((2 * jl + aSel) << 4) ^ swx);
            uint32_t bc = (((2 * jl + bSel) << 4) ^ swx);
            uint32_t a0[4], a1[4], bb[8];
            ldsm4(a0, aB0 + ac);
            ldsm4(a1, aB0 + 2048 + ac);
            ldsm4(bb + 0, bB0 + bc);
            ldsm4(bb + 4, bB0 + 2048 + bc);
#pragma unroll
            for (int n8 = 0; n8 < 4; n8++) {
                const uint32_t* bp = &bb[(n8 >> 1) * 4 + (n8 & 1) * 2];
                mma16816(acc[0][n8], a0, bp);
                mma16816(acc[1][n8], a1, bp);
            }
            ldsm4(bb + 0, bB0 + 4096 + bc);
            ldsm4(bb + 4, bB0 + 6144 + bc);
#pragma unroll
            for (int n8 = 4; n8 < 8; n8++) {
                const uint32_t* bp = &bb[((n8 - 4) >> 1) * 4 + (n8 & 1) * 2];
                mma16816(acc[0][n8], a0, bp);
                mma16816(acc[1][n8], a1, bp);
            }
        }
        if (lane == 0) MBARRIER_ARRIVE(sb + 32 + st * 8);
        if (tid == 0 && i + 2 < 81) {
            MBARRIER_WAIT_PARITY(sb + 32 + st * 8, ph);
            issue_tile(sb, i + 2, xx, yy, &tw, &tx);
        }
    }

    int g2 = lane >> 2, tc = lane & 3;
    int vb = bx * 256;
    float s = 0.f, q = 0.f;
#pragma unroll
    for (int mt = 0; mt < 2; mt++) {
#pragma unroll
        for (int n8 = 0; n8 < 8; n8++) {
            float* d = acc[mt][n8];
            int o = wm * 32 + mt * 16 + g2;
            int v = vb + wn * 64 + n8 * 8 + tc * 2;
            *(__half2*)&g_h2[o * SP + v] = __floats2half2_rn(d[0], d[1]);
            *(__half2*)&g_h2[(o + 8) * SP + v] = __floats2half2_rn(d[2], d[3]);
            s += d[0] + d[1] + d[2] + d[3];
            q = fmaf(d[0], d[0], q);
            q = fmaf(d[1], d[1], q);
            q = fmaf(d[2], d[2], q);
            q = fmaf(d[3], d[3], q);
        }
    }
    reduce2_part(s, q, &g_part2[bx * 2]);
    if (last_block(2, 256)) {
        float mu2, inv2;
        finalize_stats(g_part2, 256, 1.0 / (double)(H * SP), mu2, inv2);
        if (tid < 128) {
            float a = gn2w[tid] * inv2;
            g_a2[tid] = a;
            g_b2[tid] = gn2b[tid] - mu2 * a;
        }
    }
}

// ---------------- kernel 4: FUSED GN2+GELU -> conv3 (mma) -> SE -> GN3 -> out -------
// 256 blocks x 256 thr, 73KB dyn smem -> >=2/SM -> all 256 resident (gate-safe).
// B-tile built in smem by the GELU phase and consumed by mma; out written from regs.
#define T_B 0
#define T_A 65536
#define T_SMEM (T_A + 8192)

__global__ void __launch_bounds__(256) k_tail(const float* __restrict__ sew1,
                                              const float* __restrict__ sew2,
                                              const float* __restrict__ w3,
                                              const float* __restrict__ gn3w,
                                              const float* __restrict__ gn3b,
                                              float* __restrict__ out) {
    extern __shared__ __align__(1024) char smem[];
    uint32_t sbase = smem_u32(smem);
    __shared__ float sa2[128], sb2[128];
    __shared__ float sab3[2 * COUT];
    int tid = threadIdx.x;
    int lane = tid & 31, wid = tid >> 5;
    int bx = blockIdx.x;
    int vb = bx * 256;

    if (tid < 128) { sa2[tid] = g_a2[tid]; sb2[tid] = g_b2[tid]; }
    __syncthreads();

    // phase 1: GN2 + GELU, write fp16 into swizzled B tile (two 64c halves, 128B rows)
    {
        int vs = tid;
        for (int c = 0; c < 128; c++) {
            float val = __half2float(g_h2[c * SP + vb + vs]);
            val = geluf(fmaf(sa2[c], val, sb2[c]));
            uint32_t off = (uint32_t)(vs * 128 + (c & 63) * 2);
            *(__half*)(smem + T_B + (c >> 6) * 32768 + SWZ(off)) = __float2half(val);
        }
    }
    __syncthreads();
    // per-channel sums for SE
    if (tid < 128) {
        int c = tid;
        float s = 0.f;
        uint32_t hb = (uint32_t)((c >> 6) * 32768);
        uint32_t co = (uint32_t)((c & 63) * 2);
        for (int vs = 0; vs < 256; vs++)
            s += __half2float(*(__half*)(smem + T_B + hb + SWZ((uint32_t)(vs * 128) + co)));
        g_chsump[bx * 128 + c] = s;
    }
    // ---- grid gate 1: SE -> folded w3 fp16 ----
    if (gate_arrive(1, 256)) {
        __shared__ float m[H];
        __shared__ float t1[SED];
        if (tid < 128) {
            float cs = 0.f;
            for (int k = 0; k < 256; k++) cs += g_chsump[k * 128 + tid];
            m[tid] = cs * (1.f / 65536.f);
        }
        __syncthreads();
        if (tid < SED) {
            float acc = 0.f;
            for (int j = 0; j < H; j++) acc = fmaf(sew1[tid * H + j], m[j], acc);
            t1[tid] = geluf(acc);
        }
        __syncthreads();
        if (tid < 128) {
            float acc = 0.f;
#pragma unroll
            for (int j = 0; j < SED; j++) acc = fmaf(sew2[tid * SED + j], t1[j], acc);
            float sg = 1.f / (1.f + expf(-acc));
            for (int o = 0; o < COUT; o++)
                g_w3h[o * H + tid] = __float2half(w3[o * H + tid] * sg);
        }
        gate_release(1);
    }
    gate_wait(1, 256);

    // A tile: w3h [32 o][128 c] -> smem (two 64c halves, 128B rows, swizzled)
    for (int idx = tid; idx < 4096; idx += 256) {
        int o = idx >> 7;
        int c = idx & 127;
        uint32_t off = (uint32_t)(o * 128 + (c & 63) * 2);
        *(__half*)(smem + T_A + (c >> 6) * 4096 + SWZ(off)) = g_w3h[idx];
    }
    __syncthreads();

    // phase 2: mma (B from retained smem)
    int wm = wid & 1, wn = wid >> 1;
    float acc[8][4];
#pragma unroll
    for (int b = 0; b < 8; b++)
#pragma unroll
        for (int cc = 0; cc < 4; cc++) acc[b][cc] = 0.f;

    const uint32_t swx = (lane & 7) << 4;
    const uint32_t aSel = lane >> 4;
    const uint32_t bSel = (lane >> 3) & 1;
    const int aRow = wm * 16 + (lane & 15);
    const int bRow = wn * 64 + (lane & 7) + ((lane >> 4) << 3);

#pragma unroll
    for (int h = 0; h < 2; h++) {
        uint32_t aB = sbase + T_A + h * 4096 + aRow * 128;
        uint32_t bB = sbase + T_B + h * 32768 + bRow * 128;
#pragma unroll
        for (int j = 0; j < 4; j++) {
            uint32_t ac = (((2 * j + aSel) << 4) ^ swx);
            uint32_t bc = (((2 * j + bSel) << 4) ^ swx);
            uint32_t a0[4], bb[8];
            ldsm4(a0, aB + ac);
            ldsm4(bb + 0, bB + bc);
            ldsm4(bb + 4, bB + 2048 + bc);
#pragma unroll
            for (int n8 = 0; n8 < 4; n8++) {
                const uint32_t* bp = &bb[(n8 >> 1) * 4 + (n8 & 1) * 2];
                mma16816(acc[n8], a0, bp);
            }
            ldsm4(bb + 0, bB + 4096 + bc);
            ldsm4(bb + 4, bB + 6144 + bc);
#pragma unroll
            for (int n8 = 4; n8 < 8; n8++) {
                const uint32_t* bp = &bb[((n8 - 4) >> 1) * 4 + (n8 & 1) * 2];
                mma16816(acc[n8], a0, bp);
            }
        }
    }

    // GN3 stats from regs
    float s = 0.f, q = 0.f;
#pragma unroll
    for (int n8 = 0; n8 < 8; n8++) {
        float* d = acc[n8];
        s += d[0] + d[1] + d[2] + d[3];
        q = fmaf(d[0], d[0], q);
        q = fmaf(d[1], d[1], q);
        q = fmaf(d[2], d[2], q);
        q = fmaf(d[3], d[3], q);
    }
    reduce2_part(s, q, &g_part3[bx * 2]);
    // ---- grid gate 2: GN3 coefficients ----
    if (gate_arrive(2, 256)) {
        float mu3, inv3;
        finalize_stats(g_part3, 256, 1.0 / (double)(COUT * SP), mu3, inv3);
        if (tid < COUT) {
            float a = gn3w[tid] * inv3;
            g_a3[tid] = a;
            g_b3[tid] = gn3b[tid] - mu3 * a;
        }
        gate_release(2);
    }
    gate_wait(2, 256);
    if (tid < COUT) { sab3[tid] = g_a3[tid]; sab3[COUT + tid] = g_b3[tid]; }
    __syncthreads();

    // final GN3 from regs -> out
    int g2 = lane >> 2, tc = lane & 3;
#pragma unroll
    for (int n8 = 0; n8 < 8; n8++) {
        float* d = acc[n8];
        int o = wm * 16 + g2;
        int v = vb + wn * 64 + n8 * 8 + tc * 2;
        float a0 = sab3[o], b0 = sab3[COUT + o];
        float a8 = sab3[o + 8], b8 = sab3[COUT + o + 8];
        *(float2*)&out[o * SP + v] = make_float2(fmaf(a0, d[0], b0), fmaf(a0, d[1], b0));
        *(float2*)&out[(o + 8) * SP + v] = make_float2(fmaf(a8, d[2], b8), fmaf(a8, d[3], b8));
    }
}

// ---------------- launcher ----------------
typedef CUresult (CUDAAPI* PFN_tmapEncode)(
    CUtensorMap*, CUtensorMapDataType, cuuint32_t, void*,
    const cuuint64_t*, const cuuint64_t*, const cuuint32_t*, const cuuint32_t*,
    CUtensorMapInterleave, CUtensorMapSwizzle, CUtensorMapL2promotion, CUtensorMapFloatOOBfill);

extern "C" void kernel_launch(void* const* d_in, const int* in_sizes, int n_in,
                              void* d_out, int out_size) {
    const float* x    = (const float*)d_in[0];
    const float* g0w  = (const float*)d_in[1];
    const float* g0b  = (const float*)d_in[2];
    const float* w1   = (const float*)d_in[3];
    const float* gn1w = (const float*)d_in[4];
    const float* gn1b = (const float*)d_in[5];
    const float* w2   = (const float*)d_in[6];
    const float* gn2w = (const float*)d_in[7];
    const float* gn2b = (const float*)d_in[8];
    const float* sew1 = (const float*)d_in[9];
    const float* sew2 = (const float*)d_in[10];
    const float* w3   = (const float*)d_in[11];
    const float* gn3w = (const float*)d_in[12];
    const float* gn3b = (const float*)d_in[13];
    float* out = (float*)d_out;

    PFN_tmapEncode encode = nullptr;
    {
        void* fp = nullptr;
        cudaDriverEntryPointQueryResult qr;
        cudaGetDriverEntryPoint("cuTensorMapEncodeTiled", &fp, cudaEnableDefault, &qr);
        encode = (PFN_tmapEncode)fp;
    }

    void* pw = nullptr; void* px = nullptr;
    cudaGetSymbolAddress(&pw, g_w2h);
    cudaGetSymbolAddress(&px, g_h1h);
    CUtensorMap tw, tx;
    {
        cuuint64_t dims[3] = {128, 128, 81};
        cuuint64_t strides[2] = {256, 32768};
        cuuint32_t box[3] = {64, 128, 1};
        cuuint32_t es[3] = {1, 1, 1};
        encode(&tw, CU_TENSOR_MAP_DATA_TYPE_FLOAT16, 3, pw, dims, strides, box, es,
               CU_TENSOR_MAP_INTERLEAVE_NONE, CU_TENSOR_MAP_SWIZZLE_128B,
               CU_TENSOR_MAP_L2_PROMOTION_L2_128B, CU_TENSOR_MAP_FLOAT_OOB_FILL_NONE);
    }
    {
        cuuint64_t dims[5] = {128, 16, 16, 16, 16};
        cuuint64_t strides[4] = {256, 4096, 65536, 1048576};
        cuuint32_t box[5] = {64, 16, 16, 1, 1};
        cuuint32_t es[5] = {1, 1, 1, 1, 1};
        encode(&tx, CU_TENSOR_MAP_DATA_TYPE_FLOAT16, 5, px, dims, strides, box, es,
               CU_TENSOR_MAP_INTERLEAVE_NONE, CU_TENSOR_MAP_SWIZZLE_128B,
               CU_TENSOR_MAP_L2_PROMOTION_L2_128B, CU_TENSOR_MAP_FLOAT_OOB_FILL_NONE);
    }
    cudaFuncSetAttribute(k_conv1g, cudaFuncAttributeMaxDynamicSharedMemorySize, C1_SMEM);
    cudaFuncSetAttribute(k_conv2mma, cudaFuncAttributeMaxDynamicSharedMemorySize, SMEM_TOTAL);
    cudaFuncSetAttribute(k_tail, cudaFuncAttributeMaxDynamicSharedMemorySize, T_SMEM);

    k_stats0wt2<<<1024, 256>>>(x, w2, w1, g0w, g0b);
    k_conv1g<<<512, 128, C1_SMEM>>>(x, gn1w, gn1b);
    k_conv2mma<<<256, 512, SMEM_TOTAL>>>(tw, tx, gn2w, gn2b);
    k_tail<<<256, 256, T_SMEM>>>(sew1, sew2, w3, gn3w, gn3b, out);
}

// round 15
// speedup vs baseline: 1.0298x; 1.0298x over previous
#include <cuda_runtime.h>
#include <cuda.h>
#include <cuda_fp16.h>
#include <math.h>
#include <stdint.h>

#define SP 65536        /* 16^4 */
#define CIN 32
#define H 128
#define COUT 32
#define SED 8

// ---------------- scratch (device globals) ----------------
__device__ __align__(1024) __half g_h1h[SP * H];     // gelu1 out [v][c]; REUSED as h2^T
__device__ __align__(1024) __half g_w2h[81 * H * H]; // conv2 weights fp16 [tap][o][c]
__device__ __half g_h2[H * SP];                      // conv2 out fp16 [o][v]
__device__ float g_part0[512 * 2];
__device__ float g_part1[512 * 2];
__device__ float g_part2[256 * 2];
__device__ float g_part3[256 * 2];
__device__ float g_chsump[512 * 128];                // SE partials [blk][c]
__device__ unsigned g_cnt[8];                        // last_block counters
__device__ unsigned g_gA[4], g_gB[4], g_gR[4];       // grid gates (self-resetting)
__device__ float g_w1eff[H * CIN];
__device__ float g_bias1[H];
__device__ float g_a1[H], g_b1[H], g_a2[H], g_b2[H], g_a3[COUT], g_b3[COUT];
__device__ __half g_w3h[COUT * H];                   // SE-folded conv3 weights fp16 [o][c]

// ---------------- PTX helpers (plain sm_90/sm_80 features only) ----------------
__device__ __forceinline__ uint32_t smem_u32(const void* p) {
    uint32_t a;
    asm("{ .reg .u64 t; cvta.to.shared.u64 t, %1; cvt.u32.u64 %0, t; }" : "=r"(a) : "l"(p));
    return a;
}

#define MBARRIER_INIT(mbar, cnt) \
    asm volatile("mbarrier.init.shared.b64 [%0], %1;" :: "r"((uint32_t)(mbar)), "r"((uint32_t)(cnt)) : "memory")

#define MBARRIER_EXPECT_TX(mbar, bytes) \
    asm volatile("mbarrier.arrive.expect_tx.shared.b64 _, [%0], %1;" :: "r"((uint32_t)(mbar)), "r"((uint32_t)(bytes)) : "memory")

#define MBARRIER_ARRIVE(mbar) \
    asm volatile("mbarrier.arrive.shared.b64 _, [%0];" :: "r"((uint32_t)(mbar)) : "memory")

#define MBARRIER_WAIT_PARITY(mbar, ph) do { \
    uint32_t _m = (uint32_t)(mbar); uint32_t _p = (uint32_t)(ph); uint32_t _d; \
    asm volatile("{\n\t.reg .pred p;\n\t" \
        "mbarrier.try_wait.parity.acquire.cta.shared::cta.b64 p, [%1], %2;\n\t" \
        "selp.b32 %0, 1, 0, p;\n\t}" : "=r"(_d) : "r"(_m), "r"(_p) : "memory"); \
    if (!_d) { \
        asm volatile("{\n\t.reg .pred P1;\n\t" \
            "WL_%=:\n\t" \
            "mbarrier.try_wait.parity.acquire.cta.shared::cta.b64 P1, [%0], %1, 0x989680;\n\t" \
            "@P1 bra.uni WD_%=;\n\t" \
            "bra.uni WL_%=;\n\t" \
            "WD_%=:\n\t}" :: "r"(_m), "r"(_p) : "memory"); \
    } \
} while (0)

#define TMA_LOAD_3D(smem, map, c0, c1, c2, mbar) \
    asm volatile("cp.async.bulk.tensor.3d.shared::cta.global.tile.mbarrier::complete_tx::bytes " \
                 "[%0], [%1, {%2, %3, %4}], [%5];" \
                 :: "r"((uint32_t)(smem)), "l"(map), "r"((int)(c0)), "r"((int)(c1)), "r"((int)(c2)), \
                    "r"((uint32_t)(mbar)) : "memory")

#define TMA_LOAD_5D(smem, map, c0, c1, c2, c3, c4, mbar) \
    asm volatile("cp.async.bulk.tensor.5d.shared::cta.global.tile.mbarrier::complete_tx::bytes " \
                 "[%0], [%1, {%2, %3, %4, %5, %6}], [%7];" \
                 :: "r"((uint32_t)(smem)), "l"(map), "r"((int)(c0)), "r"((int)(c1)), "r"((int)(c2)), \
                    "r"((int)(c3)), "r"((int)(c4)), "r"((uint32_t)(mbar)) : "memory")

__device__ __forceinline__ void ldsm4(uint32_t* r, uint32_t addr) {
    asm volatile("ldmatrix.sync.aligned.m8n8.x4.shared.b16 {%0,%1,%2,%3}, [%4];"
                 : "=r"(r[0]), "=r"(r[1]), "=r"(r[2]), "=r"(r[3]) : "r"(addr));
}

__device__ __forceinline__ void mma16816(float* d, const uint32_t* a, const uint32_t* b) {
    asm volatile("mma.sync.aligned.m16n8k16.row.col.f32.f16.f16.f32 "
                 "{%0,%1,%2,%3}, {%4,%5,%6,%7}, {%8,%9}, {%0,%1,%2,%3};"
                 : "+f"(d[0]), "+f"(d[1]), "+f"(d[2]), "+f"(d[3])
                 : "r"(a[0]), "r"(a[1]), "r"(a[2]), "r"(a[3]), "r"(b[0]), "r"(b[1]));
}

__device__ __forceinline__ float geluf(float v) {
    return 0.5f * v * (1.0f + erff(v * 0.70710678118654752f));
}

#define SWZ(off) ((off) ^ (((off) >> 3) & 0x70))

__device__ __forceinline__ void reduce2_part(float s, float q, float* dst) {
    __shared__ float rA[32], rB[32];
    const unsigned full = 0xffffffffu;
#pragma unroll
    for (int off = 16; off > 0; off >>= 1) {
        s += __shfl_down_sync(full, s, off);
        q += __shfl_down_sync(full, q, off);
    }
    int lane = threadIdx.x & 31, wid = threadIdx.x >> 5;
    int nw = (blockDim.x + 31) >> 5;
    if (lane == 0) { rA[wid] = s; rB[wid] = q; }
    __syncthreads();
    if (threadIdx.x == 0) {
        float S = 0.f, Q = 0.f;
        for (int w = 0; w < nw; w++) { S += rA[w]; Q += rB[w]; }
        dst[0] = S; dst[1] = Q;
    }
}

__device__ __forceinline__ bool last_block(int idx, unsigned n) {
    __shared__ unsigned lb_done;
    __threadfence();
    if (threadIdx.x == 0) {
        unsigned old = atomicAdd(&g_cnt[idx], 1u);
        lb_done = (old == n - 1) ? 1u : 0u;
        if (lb_done) g_cnt[idx] = 0;
    }
    __syncthreads();
    if (lb_done) __threadfence();
    return lb_done != 0;
}

__device__ __forceinline__ void finalize_stats(const float* part, int n, double invN,
                                               float& mu, float& inv) {
    __shared__ float rA[32], rB[32], bc2[2];
    float s = 0.f, q = 0.f;
    for (int i = threadIdx.x; i < n; i += blockDim.x) {
        s += part[2 * i];
        q += part[2 * i + 1];
    }
    const unsigned full = 0xffffffffu;
#pragma unroll
    for (int off = 16; off > 0; off >>= 1) {
        s += __shfl_down_sync(full, s, off);
        q += __shfl_down_sync(full, q, off);
    }
    int lane = threadIdx.x & 31, wid = threadIdx.x >> 5;
    int nw = (blockDim.x + 31) >> 5;
    if (lane == 0) { rA[wid] = s; rB[wid] = q; }
    __syncthreads();
    if (threadIdx.x == 0) {
        float S = 0.f, Q = 0.f;
        for (int w = 0; w < nw; w++) { S += rA[w]; Q += rB[w]; }
        bc2[0] = S; bc2[1] = Q;
    }
    __syncthreads();
    double m = (double)bc2[0] * invN;
    double var = (double)bc2[1] * invN - m * m;
    mu = (float)m;
    inv = (float)(1.0 / sqrt(var + 1e-5));
}

// ---------------- grid gate (all blocks resident; self-resetting) ----------------
__device__ __forceinline__ bool gate_arrive(int gi, unsigned n) {
    __shared__ unsigned lastf;
    __threadfence();
    if (threadIdx.x == 0)
        lastf = (atomicAdd(&g_gA[gi], 1u) == n - 1) ? 1u : 0u;
    __syncthreads();
    return lastf != 0;
}
__device__ __forceinline__ void gate_release(int gi) {
    __threadfence();
    if (threadIdx.x == 0) atomicExch(&g_gR[gi], 1u);
}
__device__ __forceinline__ void gate_wait(int gi, unsigned n) {
    if (threadIdx.x == 0) {
        while (atomicAdd(&g_gR[gi], 0u) == 0u) __nanosleep(64);
    }
    __syncthreads();
    __threadfence();
    if (threadIdx.x == 0) {
        if (atomicAdd(&g_gB[gi], 1u) == n - 1) {
            g_gA[gi] = 0u;
            g_gB[gi] = 0u;
            atomicExch(&g_gR[gi], 0u);
        }
    }
}

// ---------------- kernel 1: stats of x + w2 transpose ----------------
__global__ void __launch_bounds__(256) k_stats0wt2(const float* __restrict__ x,
                                                   const float* __restrict__ w2,
                                                   const float* __restrict__ w1,
                                                   const float* __restrict__ g0w,
                                                   const float* __restrict__ g0b) {
    int bid = blockIdx.x;
    int tid = threadIdx.x;
    if (bid >= 512) {
        __shared__ float swt[2592];
        int base_oc = (bid - 512) * 32;
        const float* wsrc = w2 + base_oc * 81;
        for (int idx = tid; idx < 2592; idx += 256) swt[idx] = wsrc[idx];
        __syncthreads();
        for (int idx = tid; idx < 2592; idx += 256) {
            int t = idx >> 5;
            int ol = idx & 31;
            g_w2h[t * 16384 + base_oc + ol] = __float2half(swt[ol * 81 + t]);
        }
        return;
    }
    float s = 0.f, q = 0.f;
    int base = bid * 4096 + tid;
#pragma unroll
    for (int k = 0; k < 16; k++) {
        float v = x[base + k * 256];
        s += v;
        q = fmaf(v, v, q);
    }
    reduce2_part(s, q, &g_part0[bid * 2]);
    if (last_block(0, 512)) {
        float mu0, inv0;
        finalize_stats(g_part0, 512, 1.0 / (double)(CIN * SP), mu0, inv0);
        if (tid < 128) {
            int o = tid;
            float bias = 0.f;
            for (int c = 0; c < CIN; c++) {
                float a = inv0 * g0w[c];
                float b = g0b[c] - mu0 * a;
                float w = w1[o * CIN + c];
                g_w1eff[o * CIN + c] = w * a;
                bias = fmaf(w, b, bias);
            }
            g_bias1[o] = bias;
        }
    }
}

// ---------------- kernel 2: FUSED conv1 + GN1 + GELU + transpose (r14, validated) ---
#define C1_W 32768
#define C1_AB 49152
#define C1_SMEM (C1_AB + 1024)

__global__ void __launch_bounds__(128) k_conv1g(const float* __restrict__ x,
                                                const float* __restrict__ gn1w,
                                                const float* __restrict__ gn1b) {
    extern __shared__ __align__(1024) char smem[];
    float* swf = (float*)(smem + C1_W);
    float* sab = (float*)(smem + C1_AB);
    __shared__ float sb[H];
    int tid = threadIdx.x;
    for (int i = tid; i < H * CIN; i += 128) swf[i] = g_w1eff[i];
    sb[tid] = g_bias1[tid];
    __syncthreads();
    int v = blockIdx.x * 128 + tid;
    float xr[CIN];
#pragma unroll
    for (int c = 0; c < CIN; c++) xr[c] = x[c * SP + v];
    float s = 0.f, q = 0.f;
    for (int o = 0; o < H; o++) {
        const float4* wr = (const float4*)(&swf[o * CIN]);
        float a0 = 0.f, a1 = 0.f, a2 = 0.f, a3 = 0.f;
#pragma unroll
        for (int g = 0; g < 2; g++) {
            float4 w0 = wr[g * 4 + 0], w1v = wr[g * 4 + 1], w2v = wr[g * 4 + 2], w3v = wr[g * 4 + 3];
            int b = g * 16;
            a0 = fmaf(w0.x, xr[b + 0], a0);  a0 = fmaf(w0.y, xr[b + 1], a0);
            a1 = fmaf(w0.z, xr[b + 2], a1);  a1 = fmaf(w0.w, xr[b + 3], a1);
            a0 = fmaf(w1v.x, xr[b + 4], a0); a0 = fmaf(w1v.y, xr[b + 5], a0);
            a1 = fmaf(w1v.z, xr[b + 6], a1); a1 = fmaf(w1v.w, xr[b + 7], a1);
            a2 = fmaf(w2v.x, xr[b + 8], a2); a2 = fmaf(w2v.y, xr[b + 9], a2);
            a3 = fmaf(w2v.z, xr[b + 10], a3); a3 = fmaf(w2v.w, xr[b + 11], a3);
            a2 = fmaf(w3v.x, xr[b + 12], a2); a2 = fmaf(w3v.y, xr[b + 13], a2);
            a3 = fmaf(w3v.z, xr[b + 14], a3); a3 = fmaf(w3v.w, xr[b + 15], a3);
        }
        float acc = sb[o] + (a0 + a1) + (a2 + a3);
        uint32_t off = (uint32_t)(tid * 256 + o * 2);
        *(__half*)(smem + SWZ(off)) = __float2half(acc);
        s += acc;
        q = fmaf(acc, acc, q);
    }
    reduce2_part(s, q, &g_part1[blockIdx.x * 2]);
    if (gate_arrive(0, 512)) {
        float mu1, inv1;
        finalize_stats(g_part1, 512, 1.0 / (double)(H * SP), mu1, inv1);
        float a = gn1w[tid] * inv1;
        g_a1[tid] = a;
        g_b1[tid] = gn1b[tid] - mu1 * a;
        gate_release(0);
    }
    gate_wait(0, 512);
    sab[tid] = g_a1[tid];
    sab[128 + tid] = g_b1[tid];
    __syncthreads();
    uint4* dst = (uint4*)&g_h1h[(size_t)v * 128];
#pragma unroll
    for (int k = 0; k < 16; k++) {
        uint4 hv = *(uint4*)(smem + SWZ((uint32_t)(tid * 256 + k * 16)));
        uint32_t w[4] = {hv.x, hv.y, hv.z, hv.w};
        uint32_t r[4];
#pragma unroll
        for (int p = 0; p < 4; p++) {
            int c0 = k * 8 + p * 2;
            __half2 h2v = *(__half2*)&w[p];
            float f0 = geluf(fmaf(sab[c0], __half2float(h2v.x), sab[128 + c0]));
            float f1 = geluf(fmaf(sab[c0 + 1], __half2float(h2v.y), sab[128 + c0 + 1]));
            __half2 o2 = __floats2half2_rn(f0, f1);
            r[p] = *(uint32_t*)&o2;
        }
        dst[k] = make_uint4(r[0], r[1], r[2], r[3]);
    }
}

// ---------------- kernel 3: conv2 = TMA + ldmatrix + mma.sync (r12 verbatim) --------
#define NSTAGE 2
#define STAGE_BYTES 98304
#define SM_DATA 1024
#define SMEM_TOTAL (SM_DATA + NSTAGE * STAGE_BYTES)
#define TILE_TX 98304

__device__ __forceinline__ void issue_tile(uint32_t sb, int i, int xx, int yy,
                                           const CUtensorMap* tw, const CUtensorMap* tx) {
    int s = i & 1;
    uint32_t fullb = sb + s * 8;
    MBARRIER_EXPECT_TX(fullb, TILE_TX);
    int dx = i / 27;
    int r27 = i - dx * 27;
    int dy = r27 / 9;
    int r9 = r27 - dy * 9;
    int dz = r9 / 3;
    int dw = r9 - dz * 3;
    uint32_t D = sb + SM_DATA + s * STAGE_BYTES;
    TMA_LOAD_3D(D, tw, 0, 0, i, fullb);
    TMA_LOAD_3D(D + 16384, tw, 64, 0, i, fullb);
    TMA_LOAD_5D(D + 32768, tx, 0, dw - 1, dz - 1, yy + dy - 1, xx + dx - 1, fullb);
    TMA_LOAD_5D(D + 65536, tx, 64, dw - 1, dz - 1, yy + dy - 1, xx + dx - 1, fullb);
}

__global__ void __launch_bounds__(512, 1) k_conv2mma(const __grid_constant__ CUtensorMap tw,
                                                     const __grid_constant__ CUtensorMap tx,
                                                     const float* __restrict__ gn2w,
                                                     const float* __restrict__ gn2b) {
    extern __shared__ __align__(1024) char smem[];
    uint32_t sb = smem_u32(smem);
    int tid = threadIdx.x;
    int lane = tid & 31, wid = tid >> 5;
    int wm = wid & 3, wn = wid >> 2;
    int bx = blockIdx.x;
    int xx = bx >> 4, yy = bx & 15;

    if (tid == 0) {
        for (int s = 0; s < NSTAGE; s++) {
            MBARRIER_INIT(sb + s * 8, 1);
            MBARRIER_INIT(sb + 32 + s * 8, 16);
        }
    }
    __syncthreads();
    if (tid == 0) {
        issue_tile(sb, 0, xx, yy, &tw, &tx);
        issue_tile(sb, 1, xx, yy, &tw, &tx);
    }

    float acc[2][8][4];
#pragma unroll
    for (int a = 0; a < 2; a++)
#pragma unroll
        for (int b = 0; b < 8; b++)
#pragma unroll
            for (int cc = 0; cc < 4; cc++) acc[a][b][cc] = 0.f;

    const uint32_t swx = (lane & 7) << 4;
    const uint32_t aSel = lane >> 4;
    const uint32_t bSel = (lane >> 3) & 1;
    const int aRow = wm * 32 + (lane & 15);
    const int bRow = wn * 64 + (lane & 7) + ((lane >> 4) << 3);

    for (int i = 0; i < 81; i++) {
        int st = i & 1;
        int ph = (i >> 1) & 1;
        MBARRIER_WAIT_PARITY(sb + st * 8, ph);
        uint32_t D = sb + SM_DATA + st * STAGE_BYTES;
#pragma unroll
        for (int j = 0; j < 8; j++) {
            int half = j >> 2, jl = j & 3;
            uint32_t aB0 = D + half * 16384 + aRow * 128;
            uint32_t bB0 = D + 32768 + half * 32768 + bRow * 128;
            uint32_t ac = (((2 * jl + aSel) << 4) ^ swx);
            uint32_t bc = (((2 * jl + bSel) << 4) ^ swx);
            uint32_t a0[4], a1[4], bb[8];
            ldsm4(a0, aB0 + ac);
            ldsm4(a1, aB0 + 2048 + ac);
            ldsm4(bb + 0, bB0 + bc);
            ldsm4(bb + 4, bB0 + 2048 + bc);
#pragma unroll
            for (int n8 = 0; n8 < 4; n8++) {
                const uint32_t* bp = &bb[(n8 >> 1) * 4 + (n8 & 1) * 2];
                mma16816(acc[0][n8], a0, bp);
                mma16816(acc[1][n8], a1, bp);
            }
            ldsm4(bb + 0, bB0 + 4096 + bc);
            ldsm4(bb + 4, bB0 + 6144 + bc);
#pragma unroll
            for (int n8 = 4; n8 < 8; n8++) {
                const uint32_t* bp = &bb[((n8 - 4) >> 1) * 4 + (n8 & 1) * 2];
                mma16816(acc[0][n8], a0, bp);
                mma16816(acc[1][n8], a1, bp);
            }
        }
        if (lane == 0) MBARRIER_ARRIVE(sb + 32 + st * 8);
        if (tid == 0 && i + 2 < 81) {
            MBARRIER_WAIT_PARITY(sb + 32 + st * 8, ph);
            issue_tile(sb, i + 2, xx, yy, &tw, &tx);
        }
    }

    int g2 = lane >> 2, tc = lane & 3;
    int vb = bx * 256;
    float s = 0.f, q = 0.f;
#pragma unroll
    for (int mt = 0; mt < 2; mt++) {
#pragma unroll
        for (int n8 = 0; n8 < 8; n8++) {
            float* d = acc[mt][n8];
            int o = wm * 32 + mt * 16 + g2;
            int v = vb + wn * 64 + n8 * 8 + tc * 2;
            *(__half2*)&g_h2[o * SP + v] = __floats2half2_rn(d[0], d[1]);
            *(__half2*)&g_h2[(o + 8) * SP + v] = __floats2half2_rn(d[2], d[3]);
            s += d[0] + d[1] + d[2] + d[3];
            q = fmaf(d[0], d[0], q);
            q = fmaf(d[1], d[1], q);
            q = fmaf(d[2], d[2], q);
            q = fmaf(d[3], d[3], q);
        }
    }
    reduce2_part(s, q, &g_part2[bx * 2]);
    if (last_block(2, 256)) {
        float mu2, inv2;
        finalize_stats(g_part2, 256, 1.0 / (double)(H * SP), mu2, inv2);
        if (tid < 128) {
            float a = gn2w[tid] * inv2;
            g_a2[tid] = a;
            g_b2[tid] = gn2b[tid] - mu2 * a;
        }
    }
}

// ---------------- kernel 4: GN2+GELU + transpose h2 -> g_h1h; SE in last (r13) ------
__global__ void __launch_bounds__(256) k_gelu2t(const float* __restrict__ sew1,
                                                const float* __restrict__ sew2,
                                                const float* __restrict__ w3) {
    __shared__ __align__(16) __half sm[128 * 132];
    __shared__ float sa[128], sbf[128];
    int v0 = blockIdx.x * 128;
    int tid = threadIdx.x;
    if (tid < 128) { sa[tid] = g_a2[tid]; sbf[tid] = g_b2[tid]; }
    __syncthreads();
    int cs = tid >> 7;
    int vs = tid & 127;
    for (int c = cs; c < 128; c += 2) {
        float val = __half2float(g_h2[c * SP + v0 + vs]);
        val = geluf(fmaf(sa[c], val, sbf[c]));
        sm[vs * 132 + c] = __float2half(val);
    }
    __syncthreads();
    uint2* dst = (uint2*)&g_h1h[(size_t)v0 * 128];
    for (int idx = tid; idx < 4096; idx += 256) {
        int row = idx >> 5, part = idx & 31;
        const uint2* src = (const uint2*)&sm[row * 132 + part * 4];
        dst[idx] = *src;
    }
    if (tid < 128) {
        float s = 0.f;
        for (int vv = 0; vv < 128; vv++) s += __half2float(sm[vv * 132 + tid]);
        g_chsump[blockIdx.x * 128 + tid] = s;
    }
    if (last_block(3, 512)) {
        __shared__ float m[H];
        __shared__ float t1[SED];
        if (tid < 128) {
            float cssum = 0.f;
            for (int k = 0; k < 512; k++) cssum += g_chsump[k * 128 + tid];
            m[tid] = cssum * (1.f / 65536.f);
        }
        __syncthreads();
        if (tid < SED) {
            float acc = 0.f;
            for (int j = 0; j < H; j++) acc = fmaf(sew1[tid * H + j], m[j], acc);
            t1[tid] = geluf(acc);
        }
        __syncthreads();
        if (tid < 128) {
            float acc = 0.f;
#pragma unroll
            for (int j = 0; j < SED; j++) acc = fmaf(sew2[tid * SED + j], t1[j], acc);
            float sg = 1.f / (1.f + expf(-acc));
            for (int o = 0; o < COUT; o++)
                g_w3h[o * H + tid] = __float2half(w3[o * H + tid] * sg);
        }
    }
}

// ---------------- kernel 5: conv3 mma + GN3 (single gate) -> out --------------------
// 256 blocks x 256 thr, 73KB smem -> 2/SM -> all 256 resident (gate-safe).
#define SM3_A 1024
#define SM3_B 9216
#define SMEM3_TOTAL (SM3_B + 65536)   /* 74752 */

__global__ void __launch_bounds__(256) k_conv3f(const __grid_constant__ CUtensorMap tx,
                                                const float* __restrict__ gn3w,
                                                const float* __restrict__ gn3b,
                                                float* __restrict__ out) {
    extern __shared__ __align__(1024) char smem[];
    uint32_t sb = smem_u32(smem);
    __shared__ float sab3[2 * COUT];
    int tid = threadIdx.x;
    int lane = tid & 31, wid = tid >> 5;
    int wm = wid & 1, wn = wid >> 1;
    int bx = blockIdx.x;
    int xx = bx >> 4, yy = bx & 15;

    if (tid == 0) MBARRIER_INIT(sb, 1);
    __syncthreads();
    if (tid == 0) {
        MBARRIER_EXPECT_TX(sb, 65536);
        TMA_LOAD_5D(sb + SM3_B, &tx, 0, 0, 0, yy, xx, sb);
        TMA_LOAD_5D(sb + SM3_B + 32768, &tx, 64, 0, 0, yy, xx, sb);
    }
    for (int idx = tid; idx < 4096; idx += 256) {
        int o = idx >> 7;
        int c = idx & 127;
        uint32_t off = (uint32_t)(o * 128 + (c & 63) * 2);
        *(__half*)(smem + SM3_A + (c >> 6) * 4096 + SWZ(off)) = g_w3h[idx];
    }
    __syncthreads();
    MBARRIER_WAIT_PARITY(sb, 0);

    float acc[8][4];
#pragma unroll
    for (int b = 0; b < 8; b++)
#pragma unroll
        for (int cc = 0; cc < 4; cc++) acc[b][cc] = 0.f;

    const uint32_t swx = (lane & 7) << 4;
    const uint32_t aSel = lane >> 4;
    const uint32_t bSel = (lane >> 3) & 1;
    const int aRow = wm * 16 + (lane & 15);
    const int bRow = wn * 64 + (lane & 7) + ((lane >> 4) << 3);

#pragma unroll
    for (int h = 0; h < 2; h++) {
        uint32_t aB = sb + SM3_A + h * 4096 + aRow * 128;
        uint32_t bB = sb + SM3_B + h * 32768 + bRow * 128;
#pragma unroll
        for (int j = 0; j < 4; j++) {
            uint32_t ac = (((2 * j + aSel) << 4) ^ swx);
            uint32_t bc = (((2 * j + bSel) << 4) ^ swx);
            uint32_t a0[4], bb[8];
            ldsm4(a0, aB + ac);
            ldsm4(bb + 0, bB + bc);
            ldsm4(bb + 4, bB + 2048 + bc);
#pragma unroll
            for (int n8 = 0; n8 < 4; n8++) {
                const uint32_t* bp = &bb[(n8 >> 1) * 4 + (n8 & 1) * 2];
                mma16816(acc[n8], a0, bp);
            }
            ldsm4(bb + 0, bB + 4096 + bc);
            ldsm4(bb + 4, bB + 6144 + bc);
#pragma unroll
            for (int n8 = 4; n8 < 8; n8++) {
                const uint32_t* bp = &bb[((n8 - 4) >> 1) * 4 + (n8 & 1) * 2];
                mma16816(acc[n8], a0, bp);
            }
        }
    }

    // GN3 stats from regs -> single grid gate -> write out directly
    float s = 0.f, q = 0.f;
#pragma unroll
    for (int n8 = 0; n8 < 8; n8++) {
        float* d = acc[n8];
        s += d[0] + d[1] + d[2] + d[3];
        q = fmaf(d[0], d[0], q);
        q = fmaf(d[1], d[1], q);
        q = fmaf(d[2], d[2], q);
        q = fmaf(d[3], d[3], q);
    }
    reduce2_part(s, q, &g_part3[bx * 2]);
    if (gate_arrive(2, 256)) {
        float mu3, inv3;
        finalize_stats(g_part3, 256, 1.0 / (double)(COUT * SP), mu3, inv3);
        if (tid < COUT) {
            float a = gn3w[tid] * inv3;
            g_a3[tid] = a;
            g_b3[tid] = gn3b[tid] - mu3 * a;
        }
        gate_release(2);
    }
    gate_wait(2, 256);
    if (tid < COUT) { sab3[tid] = g_a3[tid]; sab3[COUT + tid] = g_b3[tid]; }
    __syncthreads();

    int g2 = lane >> 2, tc = lane & 3;
    int vb = bx * 256;
#pragma unroll
    for (int n8 = 0; n8 < 8; n8++) {
        float* d = acc[n8];
        int o = wm * 16 + g2;
        int v = vb + wn * 64 + n8 * 8 + tc * 2;
        float a0 = sab3[o], b0 = sab3[COUT + o];
        float a8 = sab3[o + 8], b8 = sab3[COUT + o + 8];
        *(float2*)&out[o * SP + v] = make_float2(fmaf(a0, d[0], b0), fmaf(a0, d[1], b0));
        *(float2*)&out[(o + 8) * SP + v] = make_float2(fmaf(a8, d[2], b8), fmaf(a8, d[3], b8));
    }
}

// ---------------- launcher ----------------
typedef CUresult (CUDAAPI* PFN_tmapEncode)(
    CUtensorMap*, CUtensorMapDataType, cuuint32_t, void*,
    const cuuint64_t*, const cuuint64_t*, const cuuint32_t*, const cuuint32_t*,
    CUtensorMapInterleave, CUtensorMapSwizzle, CUtensorMapL2promotion, CUtensorMapFloatOOBfill);

extern "C" void kernel_launch(void* const* d_in, const int* in_sizes, int n_in,
                              void* d_out, int out_size) {
    const float* x    = (const float*)d_in[0];
    const float* g0w  = (const float*)d_in[1];
    const float* g0b  = (const float*)d_in[2];
    const float* w1   = (const float*)d_in[3];
    const float* gn1w = (const float*)d_in[4];
    const float* gn1b = (const float*)d_in[5];
    const float* w2   = (const float*)d_in[6];
    const float* gn2w = (const float*)d_in[7];
    const float* gn2b = (const float*)d_in[8];
    const float* sew1 = (const float*)d_in[9];
    const float* sew2 = (const float*)d_in[10];
    const float* w3   = (const float*)d_in[11];
    const float* gn3w = (const float*)d_in[12];
    const float* gn3b = (const float*)d_in[13];
    float* out = (float*)d_out;

    PFN_tmapEncode encode = nullptr;
    {
        void* fp = nullptr;
        cudaDriverEntryPointQueryResult qr;
        cudaGetDriverEntryPoint("cuTensorMapEncodeTiled", &fp, cudaEnableDefault, &qr);
        encode = (PFN_tmapEncode)fp;
    }

    void* pw = nullptr; void* px = nullptr;
    cudaGetSymbolAddress(&pw, g_w2h);
    cudaGetSymbolAddress(&px, g_h1h);
    CUtensorMap tw, tx;
    {
        cuuint64_t dims[3] = {128, 128, 81};
        cuuint64_t strides[2] = {256, 32768};
        cuuint32_t box[3] = {64, 128, 1};
        cuuint32_t es[3] = {1, 1, 1};
        encode(&tw, CU_TENSOR_MAP_DATA_TYPE_FLOAT16, 3, pw, dims, strides, box, es,
               CU_TENSOR_MAP_INTERLEAVE_NONE, CU_TENSOR_MAP_SWIZZLE_128B,
               CU_TENSOR_MAP_L2_PROMOTION_L2_128B, CU_TENSOR_MAP_FLOAT_OOB_FILL_NONE);
    }
    {
        cuuint64_t dims[5] = {128, 16, 16, 16, 16};
        cuuint64_t strides[4] = {256, 4096, 65536, 1048576};
        cuuint32_t box[5] = {64, 16, 16, 1, 1};
        cuuint32_t es[5] = {1, 1, 1, 1, 1};
        encode(&tx, CU_TENSOR_MAP_DATA_TYPE_FLOAT16, 5, px, dims, strides, box, es,
               CU_TENSOR_MAP_INTERLEAVE_NONE, CU_TENSOR_MAP_SWIZZLE_128B,
               CU_TENSOR_MAP_L2_PROMOTION_L2_128B, CU_TENSOR_MAP_FLOAT_OOB_FILL_NONE);
    }
    cudaFuncSetAttribute(k_conv1g, cudaFuncAttributeMaxDynamicSharedMemorySize, C1_SMEM);
    cudaFuncSetAttribute(k_conv2mma, cudaFuncAttributeMaxDynamicSharedMemorySize, SMEM_TOTAL);
    cudaFuncSetAttribute(k_conv3f, cudaFuncAttributeMaxDynamicSharedMemorySize, SMEM3_TOTAL);

    k_stats0wt2<<<1024, 256>>>(x, w2, w1, g0w, g0b);
    k_conv1g<<<512, 128, C1_SMEM>>>(x, gn1w, gn1b);
    k_conv2mma<<<256, 512, SMEM_TOTAL>>>(tw, tx, gn2w, gn2b);
    k_gelu2t<<<512, 256>>>(sew1, sew2, w3);
    k_conv3f<<<256, 256, SMEM3_TOTAL>>>(tx, gn3w, gn3b, out);
}

// round 16
// speedup vs baseline: 1.0392x; 1.0091x over previous
#include <cuda_runtime.h>
#include <cuda.h>
#include <cuda_fp16.h>
#include <math.h>
#include <stdint.h>

#define SP 65536        /* 16^4 */
#define CIN 32
#define H 128
#define COUT 32
#define SED 8

// ---------------- scratch (device globals) ----------------
__device__ __align__(1024) __half g_h1h[SP * H];     // gelu1 out [v][c]; REUSED as h2^T
__device__ __align__(1024) __half g_w2h[81 * H * H]; // conv2 weights fp16 [tap][o][c]
__device__ __half g_h2[H * SP];                      // conv2 out fp16 [o][v]
__device__ float g_part0[512 * 2];
__device__ float g_part1[512 * 2];
__device__ float g_part2[256 * 2];
__device__ float g_part3[256 * 2];
__device__ float g_chsump[512 * 128];                // SE partials [blk][c]
__device__ unsigned g_cnt[8];                        // last_block counters
__device__ unsigned g_gA[4], g_gB[4], g_gR[4];       // grid gates (self-resetting)
__device__ unsigned g_job;                           // conv2 work-stealing counter
__device__ float g_w1eff[H * CIN];
__device__ float g_bias1[H];
__device__ float g_a1[H], g_b1[H], g_a2[H], g_b2[H], g_a3[COUT], g_b3[COUT];
__device__ __half g_w3h[COUT * H];                   // SE-folded conv3 weights fp16 [o][c]

// ---------------- PTX helpers (plain sm_90/sm_80 features only) ----------------
__device__ __forceinline__ uint32_t smem_u32(const void* p) {
    uint32_t a;
    asm("{ .reg .u64 t; cvta.to.shared.u64 t, %1; cvt.u32.u64 %0, t; }" : "=r"(a) : "l"(p));
    return a;
}

#define MBARRIER_INIT(mbar, cnt) \
    asm volatile("mbarrier.init.shared.b64 [%0], %1;" :: "r"((uint32_t)(mbar)), "r"((uint32_t)(cnt)) : "memory")

#define MBARRIER_EXPECT_TX(mbar, bytes) \
    asm volatile("mbarrier.arrive.expect_tx.shared.b64 _, [%0], %1;" :: "r"((uint32_t)(mbar)), "r"((uint32_t)(bytes)) : "memory")

#define MBARRIER_ARRIVE(mbar) \
    asm volatile("mbarrier.arrive.shared.b64 _, [%0];" :: "r"((uint32_t)(mbar)) : "memory")

#define MBARRIER_WAIT_PARITY(mbar, ph) do { \
    uint32_t _m = (uint32_t)(mbar); uint32_t _p = (uint32_t)(ph); uint32_t _d; \
    asm volatile("{\n\t.reg .pred p;\n\t" \
        "mbarrier.try_wait.parity.acquire.cta.shared::cta.b64 p, [%1], %2;\n\t" \
        "selp.b32 %0, 1, 0, p;\n\t}" : "=r"(_d) : "r"(_m), "r"(_p) : "memory"); \
    if (!_d) { \
        asm volatile("{\n\t.reg .pred P1;\n\t" \
            "WL_%=:\n\t" \
            "mbarrier.try_wait.parity.acquire.cta.shared::cta.b64 P1, [%0], %1, 0x989680;\n\t" \
            "@P1 bra.uni WD_%=;\n\t" \
            "bra.uni WL_%=;\n\t" \
            "WD_%=:\n\t}" :: "r"(_m), "r"(_p) : "memory"); \
    } \
} while (0)

#define TMA_LOAD_3D(smem, map, c0, c1, c2, mbar) \
    asm volatile("cp.async.bulk.tensor.3d.shared::cta.global.tile.mbarrier::complete_tx::bytes " \
                 "[%0], [%1, {%2, %3, %4}], [%5];" \
                 :: "r"((uint32_t)(smem)), "l"(map), "r"((int)(c0)), "r"((int)(c1)), "r"((int)(c2)), \
                    "r"((uint32_t)(mbar)) : "memory")

#define TMA_LOAD_5D(smem, map, c0, c1, c2, c3, c4, mbar) \
    asm volatile("cp.async.bulk.tensor.5d.shared::cta.global.tile.mbarrier::complete_tx::bytes " \
                 "[%0], [%1, {%2, %3, %4, %5, %6}], [%7];" \
                 :: "r"((uint32_t)(smem)), "l"(map), "r"((int)(c0)), "r"((int)(c1)), "r"((int)(c2)), \
                    "r"((int)(c3)), "r"((int)(c4)), "r"((uint32_t)(mbar)) : "memory")

__device__ __forceinline__ void ldsm4(uint32_t* r, uint32_t addr) {
    asm volatile("ldmatrix.sync.aligned.m8n8.x4.shared.b16 {%0,%1,%2,%3}, [%4];"
                 : "=r"(r[0]), "=r"(r[1]), "=r"(r[2]), "=r"(r[3]) : "r"(addr));
}

__device__ __forceinline__ void mma16816(float* d, const uint32_t* a, const uint32_t* b) {
    asm volatile("mma.sync.aligned.m16n8k16.row.col.f32.f16.f16.f32 "
                 "{%0,%1,%2,%3}, {%4,%5,%6,%7}, {%8,%9}, {%0,%1,%2,%3};"
                 : "+f"(d[0]), "+f"(d[1]), "+f"(d[2]), "+f"(d[3])
                 : "r"(a[0]), "r"(a[1]), "r"(a[2]), "r"(a[3]), "r"(b[0]), "r"(b[1]));
}

__device__ __forceinline__ float geluf(float v) {
    return 0.5f * v * (1.0f + erff(v * 0.70710678118654752f));
}

#define SWZ(off) ((off) ^ (((off) >> 3) & 0x70))

__device__ __forceinline__ void reduce2_part(float s, float q, float* dst) {
    __shared__ float rA[32], rB[32];
    const unsigned full = 0xffffffffu;
#pragma unroll
    for (int off = 16; off > 0; off >>= 1) {
        s += __shfl_down_sync(full, s, off);
        q += __shfl_down_sync(full, q, off);
    }
    int lane = threadIdx.x & 31, wid = threadIdx.x >> 5;
    int nw = (blockDim.x + 31) >> 5;
    if (lane == 0) { rA[wid] = s; rB[wid] = q; }
    __syncthreads();
    if (threadIdx.x == 0) {
        float S = 0.f, Q = 0.f;
        for (int w = 0; w < nw; w++) { S += rA[w]; Q += rB[w]; }
        dst[0] = S; dst[1] = Q;
    }
    __syncthreads();
}

__device__ __forceinline__ bool last_block(int idx, unsigned n) {
    __shared__ unsigned lb_done;
    __threadfence();
    if (threadIdx.x == 0) {
        unsigned old = atomicAdd(&g_cnt[idx], 1u);
        lb_done = (old == n - 1) ? 1u : 0u;
        if (lb_done) g_cnt[idx] = 0;
    }
    __syncthreads();
    if (lb_done) __threadfence();
    return lb_done != 0;
}

__device__ __forceinline__ void finalize_stats(const float* part, int n, double invN,
                                               float& mu, float& inv) {
    __shared__ float rA[32], rB[32], bc2[2];
    float s = 0.f, q = 0.f;
    for (int i = threadIdx.x; i < n; i += blockDim.x) {
        s += part[2 * i];
        q += part[2 * i + 1];
    }
    const unsigned full = 0xffffffffu;
#pragma unroll
    for (int off = 16; off > 0; off >>= 1) {
        s += __shfl_down_sync(full, s, off);
        q += __shfl_down_sync(full, q, off);
    }
    int lane = threadIdx.x & 31, wid = threadIdx.x >> 5;
    int nw = (blockDim.x + 31) >> 5;
    if (lane == 0) { rA[wid] = s; rB[wid] = q; }
    __syncthreads();
    if (threadIdx.x == 0) {
        float S = 0.f, Q = 0.f;
        for (int w = 0; w < nw; w++) { S += rA[w]; Q += rB[w]; }
        bc2[0] = S; bc2[1] = Q;
    }
    __syncthreads();
    double m = (double)bc2[0] * invN;
    double var = (double)bc2[1] * invN - m * m;
    mu = (float)m;
    inv = (float)(1.0 / sqrt(var + 1e-5));
}

// ---------------- grid gate (all blocks resident; self-resetting) ----------------
__device__ __forceinline__ bool gate_arrive(int gi, unsigned n) {
    __shared__ unsigned lastf;
    __threadfence();
    if (threadIdx.x == 0)
        lastf = (atomicAdd(&g_gA[gi], 1u) == n - 1) ? 1u : 0u;
    __syncthreads();
    return lastf != 0;
}
__device__ __forceinline__ void gate_release(int gi) {
    __threadfence();
    if (threadIdx.x == 0) atomicExch(&g_gR[gi], 1u);
}
__device__ __forceinline__ void gate_wait(int gi, unsigned n) {
    if (threadIdx.x == 0) {
        while (atomicAdd(&g_gR[gi], 0u) == 0u) __nanosleep(64);
    }
    __syncthreads();
    __threadfence();
    if (threadIdx.x == 0) {
        if (atomicAdd(&g_gB[gi], 1u) == n - 1) {
            g_gA[gi] = 0u;
            g_gB[gi] = 0u;
            atomicExch(&g_gR[gi], 0u);
        }
    }
}

// ---------------- kernel 1: stats of x + w2 transpose (+ reset conv2 job counter) ---
__global__ void __launch_bounds__(256) k_stats0wt2(const float* __restrict__ x,
                                                   const float* __restrict__ w2,
                                                   const float* __restrict__ w1,
                                                   const float* __restrict__ g0w,
                                                   const float* __restrict__ g0b) {
    int bid = blockIdx.x;
    int tid = threadIdx.x;
    if (bid == 0 && tid == 0) g_job = 0u;   // stream-ordered reset for persistent conv2
    if (bid >= 512) {
        __shared__ float swt[2592];
        int base_oc = (bid - 512) * 32;
        const float* wsrc = w2 + base_oc * 81;
        for (int idx = tid; idx < 2592; idx += 256) swt[idx] = wsrc[idx];
        __syncthreads();
        for (int idx = tid; idx < 2592; idx += 256) {
            int t = idx >> 5;
            int ol = idx & 31;
            g_w2h[t * 16384 + base_oc + ol] = __float2half(swt[ol * 81 + t]);
        }
        return;
    }
    float s = 0.f, q = 0.f;
    int base = bid * 4096 + tid;
#pragma unroll
    for (int k = 0; k < 16; k++) {
        float v = x[base + k * 256];
        s += v;
        q = fmaf(v, v, q);
    }
    reduce2_part(s, q, &g_part0[bid * 2]);
    if (last_block(0, 512)) {
        float mu0, inv0;
        finalize_stats(g_part0, 512, 1.0 / (double)(CIN * SP), mu0, inv0);
        if (tid < 128) {
            int o = tid;
            float bias = 0.f;
            for (int c = 0; c < CIN; c++) {
                float a = inv0 * g0w[c];
                float b = g0b[c] - mu0 * a;
                float w = w1[o * CIN + c];
                g_w1eff[o * CIN + c] = w * a;
                bias = fmaf(w, b, bias);
            }
            g_bias1[o] = bias;
        }
    }
}

// ---------------- kernel 2: FUSED conv1 + GN1 + GELU + transpose (r14, validated) ---
#define C1_W 32768
#define C1_AB 49152
#define C1_SMEM (C1_AB + 1024)

__global__ void __launch_bounds__(128) k_conv1g(const float* __restrict__ x,
                                                const float* __restrict__ gn1w,
                                                const float* __restrict__ gn1b) {
    extern __shared__ __align__(1024) char smem[];
    float* swf = (float*)(smem + C1_W);
    float* sab = (float*)(smem + C1_AB);
    __shared__ float sb[H];
    int tid = threadIdx.x;
    for (int i = tid; i < H * CIN; i += 128) swf[i] = g_w1eff[i];
    sb[tid] = g_bias1[tid];
    __syncthreads();
    int v = blockIdx.x * 128 + tid;
    float xr[CIN];
#pragma unroll
    for (int c = 0; c < CIN; c++) xr[c] = x[c * SP + v];
    float s = 0.f, q = 0.f;
    for (int o = 0; o < H; o++) {
        const float4* wr = (const float4*)(&swf[o * CIN]);
        float a0 = 0.f, a1 = 0.f, a2 = 0.f, a3 = 0.f;
#pragma unroll
        for (int g = 0; g < 2; g++) {
            float4 w0 = wr[g * 4 + 0], w1v = wr[g * 4 + 1], w2v = wr[g * 4 + 2], w3v = wr[g * 4 + 3];
            int b = g * 16;
            a0 = fmaf(w0.x, xr[b + 0], a0);  a0 = fmaf(w0.y, xr[b + 1], a0);
            a1 = fmaf(w0.z, xr[b + 2], a1);  a1 = fmaf(w0.w, xr[b + 3], a1);
            a0 = fmaf(w1v.x, xr[b + 4], a0); a0 = fmaf(w1v.y, xr[b + 5], a0);
            a1 = fmaf(w1v.z, xr[b + 6], a1); a1 = fmaf(w1v.w, xr[b + 7], a1);
            a2 = fmaf(w2v.x, xr[b + 8], a2); a2 = fmaf(w2v.y, xr[b + 9], a2);
            a3 = fmaf(w2v.z, xr[b + 10], a3); a3 = fmaf(w2v.w, xr[b + 11], a3);
            a2 = fmaf(w3v.x, xr[b + 12], a2); a2 = fmaf(w3v.y, xr[b + 13], a2);
            a3 = fmaf(w3v.z, xr[b + 14], a3); a3 = fmaf(w3v.w, xr[b + 15], a3);
        }
        float acc = sb[o] + (a0 + a1) + (a2 + a3);
        uint32_t off = (uint32_t)(tid * 256 + o * 2);
        *(__half*)(smem + SWZ(off)) = __float2half(acc);
        s += acc;
        q = fmaf(acc, acc, q);
    }
    reduce2_part(s, q, &g_part1[blockIdx.x * 2]);
    if (gate_arrive(0, 512)) {
        float mu1, inv1;
        finalize_stats(g_part1, 512, 1.0 / (double)(H * SP), mu1, inv1);
        float a = gn1w[tid] * inv1;
        g_a1[tid] = a;
        g_b1[tid] = gn1b[tid] - mu1 * a;
        gate_release(0);
    }
    gate_wait(0, 512);
    sab[tid] = g_a1[tid];
    sab[128 + tid] = g_b1[tid];
    __syncthreads();
    uint4* dst = (uint4*)&g_h1h[(size_t)v * 128];
#pragma unroll
    for (int k = 0; k < 16; k++) {
        uint4 hv = *(uint4*)(smem + SWZ((uint32_t)(tid * 256 + k * 16)));
        uint32_t w[4] = {hv.x, hv.y, hv.z, hv.w};
        uint32_t r[4];
#pragma unroll
        for (int p = 0; p < 4; p++) {
            int c0 = k * 8 + p * 2;
            __half2 h2v = *(__half2*)&w[p];
            float f0 = geluf(fmaf(sab[c0], __half2float(h2v.x), sab[128 + c0]));
            float f1 = geluf(fmaf(sab[c0 + 1], __half2float(h2v.y), sab[128 + c0 + 1]));
            __half2 o2 = __floats2half2_rn(f0, f1);
            r[p] = *(uint32_t*)&o2;
        }
        dst[k] = make_uint4(r[0], r[1], r[2], r[3]);
    }
}

// ---------------- kernel 3: conv2 PERSISTENT (148 CTAs, atomic work-stealing) -------
#define NSTAGE 2
#define STAGE_BYTES 98304
#define SM_DATA 1024
#define SMEM_TOTAL (SM_DATA + NSTAGE * STAGE_BYTES)
#define TILE_TX 98304
#define NJOBS 256

__device__ __forceinline__ void issue_tile2(uint32_t sb, int st, int i, int xx, int yy,
                                            const CUtensorMap* tw, const CUtensorMap* tx) {
    uint32_t fullb = sb + st * 8;
    MBARRIER_EXPECT_TX(fullb, TILE_TX);
    int dx = i / 27;
    int r27 = i - dx * 27;
    int dy = r27 / 9;
    int r9 = r27 - dy * 9;
    int dz = r9 / 3;
    int dw = r9 - dz * 3;
    uint32_t D = sb + SM_DATA + st * STAGE_BYTES;
    TMA_LOAD_3D(D, tw, 0, 0, i, fullb);
    TMA_LOAD_3D(D + 16384, tw, 64, 0, i, fullb);
    TMA_LOAD_5D(D + 32768, tx, 0, dw - 1, dz - 1, yy + dy - 1, xx + dx - 1, fullb);
    TMA_LOAD_5D(D + 65536, tx, 64, dw - 1, dz - 1, yy + dy - 1, xx + dx - 1, fullb);
}

__global__ void __launch_bounds__(512, 1) k_conv2mma(const __grid_constant__ CUtensorMap tw,
                                                     const __grid_constant__ CUtensorMap tx,
                                                     const float* __restrict__ gn2w,
                                                     const float* __restrict__ gn2b) {
    extern __shared__ __align__(1024) char smem[];
    uint32_t sb = smem_u32(smem);
    __shared__ int sjob;
    int tid = threadIdx.x;
    int lane = tid & 31, wid = tid >> 5;
    int wm = wid & 3, wn = wid >> 2;

    if (tid == 0) {
        for (int s = 0; s < NSTAGE; s++) {
            MBARRIER_INIT(sb + s * 8, 1);                 // full: tx-based
            MBARRIER_INIT(sb + 32 + s * 8, 16);           // empty: 1 arrive/warp (lane 0)
        }
    }
    __syncthreads();

    const uint32_t swx = (lane & 7) << 4;
    const uint32_t aSel = lane >> 4;
    const uint32_t bSel = (lane >> 3) & 1;
    const int aRow = wm * 32 + (lane & 15);
    const int bRow = wn * 64 + (lane & 7) + ((lane >> 4) << 3);

    unsigned gt = 0;                 // producer: global tiles issued (tid0)
    unsigned ct = 0;                 // consumer: global tiles consumed (all threads, lockstep)
    int eph0 = 0, eph1 = 0;          // empty-barrier phases (producer)
    int cph0 = 0, cph1 = 0;          // full-barrier phases (consumer)

    for (;;) {
        if (tid == 0) sjob = (int)atomicAdd(&g_job, 1u);
        __syncthreads();
        int job = sjob;
        if (job >= NJOBS) break;
        int xx = job >> 4, yy = job & 15;

        // producer: prime 2 tiles of this job
        if (tid == 0) {
#pragma unroll
            for (int t = 0; t < 2; t++) {
                int st = (int)(gt & 1u);
                if (gt >= 2) {
                    if (st == 0) { MBARRIER_WAIT_PARITY(sb + 32, eph0); eph0 ^= 1; }
                    else         { MBARRIER_WAIT_PARITY(sb + 40, eph1); eph1 ^= 1; }
                }
                issue_tile2(sb, st, t, xx, yy, &tw, &tx);
                gt++;
            }
        }

        float acc[2][8][4];
#pragma unroll
        for (int a = 0; a < 2; a++)
#pragma unroll
            for (int b = 0; b < 8; b++)
#pragma unroll
                for (int cc = 0; cc < 4; cc++) acc[a][b][cc] = 0.f;

        for (int i = 0; i < 81; i++) {
            int st = (int)(ct & 1u);
            if (st == 0) { MBARRIER_WAIT_PARITY(sb + 0, cph0); cph0 ^= 1; }
            else         { MBARRIER_WAIT_PARITY(sb + 8, cph1); cph1 ^= 1; }
            ct++;
            uint32_t D = sb + SM_DATA + st * STAGE_BYTES;
#pragma unroll
            for (int j = 0; j < 8; j++) {
                int half = j >> 2, jl = j & 3;
                uint32_t aB0 = D + half * 16384 + aRow * 128;
                uint32_t bB0 = D + 32768 + half * 32768 + bRow * 128;
                uint32_t ac = (((2 * jl + aSel) << 4) ^ swx);
                uint32_t bc = (((2 * jl + bSel) << 4) ^ swx);
                uint32_t a0[4], a1[4], bb[8];
                ldsm4(a0, aB0 + ac);
                ldsm4(a1, aB0 + 2048 + ac);
                ldsm4(bb + 0, bB0 + bc);
                ldsm4(bb + 4, bB0 + 2048 + bc);
#pragma unroll
                for (int n8 = 0; n8 < 4; n8++) {
                    const uint32_t* bp = &bb[(n8 >> 1) * 4 + (n8 & 1) * 2];
                    mma16816(acc[0][n8], a0, bp);
                    mma16816(acc[1][n8], a1, bp);
                }
                ldsm4(bb + 0, bB0 + 4096 + bc);
                ldsm4(bb + 4, bB0 + 6144 + bc);
#pragma unroll
                for (int n8 = 4; n8 < 8; n8++) {
                    const uint32_t* bp = &bb[((n8 - 4) >> 1) * 4 + (n8 & 1) * 2];
                    mma16816(acc[0][n8], a0, bp);
                    mma16816(acc[1][n8], a1, bp);
                }
            }
            if (lane == 0) MBARRIER_ARRIVE(sb + 32 + st * 8);
            if (tid == 0 && i + 2 < 81) {
                int st2 = (int)(gt & 1u);
                if (st2 == 0) { MBARRIER_WAIT_PARITY(sb + 32, eph0); eph0 ^= 1; }
                else          { MBARRIER_WAIT_PARITY(sb + 40, eph1); eph1 ^= 1; }
                issue_tile2(sb, st2, i + 2, xx, yy, &tw, &tx);
                gt++;
            }
        }

        // epilogue: write fp16 h2 [o][v] + GN2 stats partial for this job
        int g2 = lane >> 2, tc = lane & 3;
        int vb = job * 256;
        float s = 0.f, q = 0.f;
#pragma unroll
        for (int mt = 0; mt < 2; mt++) {
#pragma unroll
            for (int n8 = 0; n8 < 8; n8++) {
                float* d = acc[mt][n8];
                int o = wm * 32 + mt * 16 + g2;
                int v = vb + wn * 64 + n8 * 8 + tc * 2;
                *(__half2*)&g_h2[o * SP + v] = __floats2half2_rn(d[0], d[1]);
                *(__half2*)&g_h2[(o + 8) * SP + v] = __floats2half2_rn(d[2], d[3]);
                s += d[0] + d[1] + d[2] + d[3];
                q = fmaf(d[0], d[0], q);
                q = fmaf(d[1], d[1], q);
                q = fmaf(d[2], d[2], q);
                q = fmaf(d[3], d[3], q);
            }
        }
        reduce2_part(s, q, &g_part2[job * 2]);
        if (last_block(2, NJOBS)) {   // counts completed jobs
            float mu2, inv2;
            finalize_stats(g_part2, NJOBS, 1.0 / (double)(H * SP), mu2, inv2);
            if (tid < 128) {
                float a = gn2w[tid] * inv2;
                g_a2[tid] = a;
                g_b2[tid] = gn2b[tid] - mu2 * a;
            }
        }
    }
}

// ---------------- kernel 4: GN2+GELU + transpose h2 -> g_h1h; SE in last ------------
__global__ void __launch_bounds__(256) k_gelu2t(const float* __restrict__ sew1,
                                                const float* __restrict__ sew2,
                                                const float* __restrict__ w3) {
    __shared__ __align__(16) __half sm[128 * 132];
    __shared__ float sa[128], sbf[128];
    __shared__ float psum[256];
    int v0 = blockIdx.x * 128;
    int tid = threadIdx.x;
    if (tid < 128) { sa[tid] = g_a2[tid]; sbf[tid] = g_b2[tid]; }
    __syncthreads();
    int cs = tid >> 7;
    int vs = tid & 127;
    for (int c = cs; c < 128; c += 2) {
        float val = __half2float(g_h2[c * SP + v0 + vs]);
        val = geluf(fmaf(sa[c], val, sbf[c]));
        sm[vs * 132 + c] = __float2half(val);
    }
    __syncthreads();
    uint2* dst = (uint2*)&g_h1h[(size_t)v0 * 128];
    for (int idx = tid; idx < 4096; idx += 256) {
        int row = idx >> 5, part = idx & 31;
        const uint2* src = (const uint2*)&sm[row * 132 + part * 4];
        dst[idx] = *src;
    }
    // per-channel sums: all 256 threads (two 64-voxel halves)
    {
        int c = tid & 127;
        int hf = tid >> 7;
        float s = 0.f;
        int vvb = hf * 64;
        for (int vv = vvb; vv < vvb + 64; vv++) s += __half2float(sm[vv * 132 + c]);
        psum[tid] = s;
    }
    __syncthreads();
    if (tid < 128) g_chsump[blockIdx.x * 128 + tid] = psum[tid] + psum[tid + 128];
    if (last_block(3, 512)) {
        __shared__ float m[H];
        __shared__ float t1[SED];
        if (tid < 128) {
            float cssum = 0.f;
            for (int k = 0; k < 512; k++) cssum += g_chsump[k * 128 + tid];
            m[tid] = cssum * (1.f / 65536.f);
        }
        __syncthreads();
        if (tid < SED) {
            float acc = 0.f;
            for (int j = 0; j < H; j++) acc = fmaf(sew1[tid * H + j], m[j], acc);
            t1[tid] = geluf(acc);
        }
        __syncthreads();
        if (tid < 128) {
            float acc = 0.f;
#pragma unroll
            for (int j = 0; j < SED; j++) acc = fmaf(sew2[tid * SED + j], t1[j], acc);
            float sg = 1.f / (1.f + expf(-acc));
            for (int o = 0; o < COUT; o++)
                g_w3h[o * H + tid] = __float2half(w3[o * H + tid] * sg);
        }
    }
}

// ---------------- kernel 5: conv3 mma + GN3 (single gate) -> out --------------------
#define SM3_A 1024
#define SM3_B 9216
#define SMEM3_TOTAL (SM3_B + 65536)

__global__ void __launch_bounds__(256) k_conv3f(const __grid_constant__ CUtensorMap tx,
                                                const float* __restrict__ gn3w,
                                                const float* __restrict__ gn3b,
                                                float* __restrict__ out) {
    extern __shared__ __align__(1024) char smem[];
    uint32_t sb = smem_u32(smem);
    __shared__ float sab3[2 * COUT];
    int tid = threadIdx.x;
    int lane = tid & 31, wid = tid >> 5;
    int wm = wid & 1, wn = wid >> 1;
    int bx = blockIdx.x;
    int xx = bx >> 4, yy = bx & 15;

    if (tid == 0) MBARRIER_INIT(sb, 1);
    __syncthreads();
    if (tid == 0) {
        MBARRIER_EXPECT_TX(sb, 65536);
        TMA_LOAD_5D(sb + SM3_B, &tx, 0, 0, 0, yy, xx, sb);
        TMA_LOAD_5D(sb + SM3_B + 32768, &tx, 64, 0, 0, yy, xx, sb);
    }
    for (int idx = tid; idx < 4096; idx += 256) {
        int o = idx >> 7;
        int c = idx & 127;
        uint32_t off = (uint32_t)(o * 128 + (c & 63) * 2);
        *(__half*)(smem + SM3_A + (c >> 6) * 4096 + SWZ(off)) = g_w3h[idx];
    }
    __syncthreads();
    MBARRIER_WAIT_PARITY(sb, 0);

    float acc[8][4];
#pragma unroll
    for (int b = 0; b < 8; b++)
#pragma unroll
        for (int cc = 0; cc < 4; cc++) acc[b][cc] = 0.f;

    const uint32_t swx = (lane & 7) << 4;
    const uint32_t aSel = lane >> 4;
    const uint32_t bSel = (lane >> 3) & 1;
    const int aRow = wm * 16 + (lane & 15);
    const int bRow = wn * 64 + (lane & 7) + ((lane >> 4) << 3);

#pragma unroll
    for (int h = 0; h < 2; h++) {
        uint32_t aB = sb + SM3_A + h * 4096 + aRow * 128;
        uint32_t bB = sb + SM3_B + h * 32768 + bRow * 128;
#pragma unroll
        for (int j = 0; j < 4; j++) {
            uint32_t ac = (((2 * j + aSel) << 4) ^ swx);
            uint32_t bc = (((2 * j + bSel) << 4) ^ swx);
            uint32_t a0[4], bb[8];
            ldsm4(a0, aB + ac);
            ldsm4(bb + 0, bB + bc);
            ldsm4(bb + 4, bB + 2048 + bc);
#pragma unroll
            for (int n8 = 0; n8 < 4; n8++) {
                const uint32_t* bp = &bb[(n8 >> 1) * 4 + (n8 & 1) * 2];
                mma16816(acc[n8], a0, bp);
            }
            ldsm4(bb + 0, bB + 4096 + bc);
            ldsm4(bb + 4, bB + 6144 + bc);
#pragma unroll
            for (int n8 = 4; n8 < 8; n8++) {
                const uint32_t* bp = &bb[((n8 - 4) >> 1) * 4 + (n8 & 1) * 2];
                mma16816(acc[n8], a0, bp);
            }
        }
    }

    float s = 0.f, q = 0.f;
#pragma unroll
    for (int n8 = 0; n8 < 8; n8++) {
        float* d = acc[n8];
        s += d[0] + d[1] + d[2] + d[3];
        q = fmaf(d[0], d[0], q);
        q = fmaf(d[1], d[1], q);
        q = fmaf(d[2], d[2], q);
        q = fmaf(d[3], d[3], q);
    }
    reduce2_part(s, q, &g_part3[bx * 2]);
    if (gate_arrive(2, 256)) {
        float mu3, inv3;
        finalize_stats(g_part3, 256, 1.0 / (double)(COUT * SP), mu3, inv3);
        if (tid < COUT) {
            float a = gn3w[tid] * inv3;
            g_a3[tid] = a;
            g_b3[tid] = gn3b[tid] - mu3 * a;
        }
        gate_release(2);
    }
    gate_wait(2, 256);
    if (tid < COUT) { sab3[tid] = g_a3[tid]; sab3[COUT + tid] = g_b3[tid]; }
    __syncthreads();

    int g2 = lane >> 2, tc = lane & 3;
    int vb = bx * 256;
#pragma unroll
    for (int n8 = 0; n8 < 8; n8++) {
        float* d = acc[n8];
        int o = wm * 16 + g2;
        int v = vb + wn * 64 + n8 * 8 + tc * 2;
        float a0 = sab3[o], b0 = sab3[COUT + o];
        float a8 = sab3[o + 8], b8 = sab3[COUT + o + 8];
        *(float2*)&out[o * SP + v] = make_float2(fmaf(a0, d[0], b0), fmaf(a0, d[1], b0));
        *(float2*)&out[(o + 8) * SP + v] = make_float2(fmaf(a8, d[2], b8), fmaf(a8, d[3], b8));
    }
}

// ---------------- launcher ----------------
typedef CUresult (CUDAAPI* PFN_tmapEncode)(
    CUtensorMap*, CUtensorMapDataType, cuuint32_t, void*,
    const cuuint64_t*, const cuuint64_t*, const cuuint32_t*, const cuuint32_t*,
    CUtensorMapInterleave, CUtensorMapSwizzle, CUtensorMapL2promotion, CUtensorMapFloatOOBfill);

extern "C" void kernel_launch(void* const* d_in, const int* in_sizes, int n_in,
                              void* d_out, int out_size) {
    const float* x    = (const float*)d_in[0];
    const float* g0w  = (const float*)d_in[1];
    const float* g0b  = (const float*)d_in[2];
    const float* w1   = (const float*)d_in[3];
    const float* gn1w = (const float*)d_in[4];
    const float* gn1b = (const float*)d_in[5];
    const float* w2   = (const float*)d_in[6];
    const float* gn2w = (const float*)d_in[7];
    const float* gn2b = (const float*)d_in[8];
    const float* sew1 = (const float*)d_in[9];
    const float* sew2 = (const float*)d_in[10];
    const float* w3   = (const float*)d_in[11];
    const float* gn3w = (const float*)d_in[12];
    const float* gn3b = (const float*)d_in[13];
    float* out = (float*)d_out;

    PFN_tmapEncode encode = nullptr;
    {
        void* fp = nullptr;
        cudaDriverEntryPointQueryResult qr;
        cudaGetDriverEntryPoint("cuTensorMapEncodeTiled", &fp, cudaEnableDefault, &qr);
        encode = (PFN_tmapEncode)fp;
    }

    void* pw = nullptr; void* px = nullptr;
    cudaGetSymbolAddress(&pw, g_w2h);
    cudaGetSymbolAddress(&px, g_h1h);
    CUtensorMap tw, tx;
    {
        cuuint64_t dims[3] = {128, 128, 81};
        cuuint64_t strides[2] = {256, 32768};
        cuuint32_t box[3] = {64, 128, 1};
        cuuint32_t es[3] = {1, 1, 1};
        encode(&tw, CU_TENSOR_MAP_DATA_TYPE_FLOAT16, 3, pw, dims, strides, box, es,
               CU_TENSOR_MAP_INTERLEAVE_NONE, CU_TENSOR_MAP_SWIZZLE_128B,
               CU_TENSOR_MAP_L2_PROMOTION_L2_128B, CU_TENSOR_MAP_FLOAT_OOB_FILL_NONE);
    }
    {
        cuuint64_t dims[5] = {128, 16, 16, 16, 16};
        cuuint64_t strides[4] = {256, 4096, 65536, 1048576};
        cuuint32_t box[5] = {64, 16, 16, 1, 1};
        cuuint32_t es[5] = {1, 1, 1, 1, 1};
        encode(&tx, CU_TENSOR_MAP_DATA_TYPE_FLOAT16, 5, px, dims, strides, box, es,
               CU_TENSOR_MAP_INTERLEAVE_NONE, CU_TENSOR_MAP_SWIZZLE_128B,
               CU_TENSOR_MAP_L2_PROMOTION_L2_128B, CU_TENSOR_MAP_FLOAT_OOB_FILL_NONE);
    }
    cudaFuncSetAttribute(k_conv1g, cudaFuncAttributeMaxDynamicSharedMemorySize, C1_SMEM);
    cudaFuncSetAttribute(k_conv2mma, cudaFuncAttributeMaxDynamicSharedMemorySize, SMEM_TOTAL);
    cudaFuncSetAttribute(k_conv3f, cudaFuncAttributeMaxDynamicSharedMemorySize, SMEM3_TOTAL);

    k_stats0wt2<<<1024, 256>>>(x, w2, w1, g0w, g0b);
    k_conv1g<<<512, 128, C1_SMEM>>>(x, gn1w, gn1b);
    k_conv2mma<<<148, 512, SMEM_TOTAL>>>(tw, tx, gn2w, gn2b);   // persistent
    k_gelu2t<<<512, 256>>>(sew1, sew2, w3);
    k_conv3f<<<256, 256, SMEM3_TOTAL>>>(tx, gn3w, gn3b, out);
}

// round 17
// speedup vs baseline: 1.0479x; 1.0083x over previous
#include <cuda_runtime.h>
#include <cuda.h>
#include <cuda_fp16.h>
#include <math.h>
#include <stdint.h>

#define SP 65536        /* 16^4 */
#define CIN 32
#define H 128
#define COUT 32
#define SED 8

// ---------------- scratch (device globals) ----------------
__device__ __align__(1024) __half g_h1h[SP * H];     // gelu1 out [v][c]; REUSED as h2^T
__device__ __align__(1024) __half g_w2h[81 * H * H]; // conv2 weights fp16 [tap][o][c]
__device__ __half g_h2[H * SP];                      // conv2 out fp16 [o][v]
__device__ float g_part0[512 * 2];
__device__ float g_part1[512 * 2];
__device__ float g_part2[256 * 2];
__device__ float g_part3[256 * 2];
__device__ float g_chsump[512 * 128];                // SE partials [blk][c]
__device__ unsigned g_cnt[8];                        // last_block counters
__device__ unsigned g_gA[4], g_gB[4], g_gR[4];       // grid gates (self-resetting)
__device__ unsigned g_job;                           // conv2 work-stealing counter
__device__ float g_w1eff[H * CIN];
__device__ float g_bias1[H];
__device__ float g_a1[H], g_b1[H], g_a2[H], g_b2[H], g_a3[COUT], g_b3[COUT];
__device__ __half g_w3h[COUT * H];                   // SE-folded conv3 weights fp16 [o][c]

// ---------------- PTX helpers (plain sm_90/sm_80 features only) ----------------
__device__ __forceinline__ uint32_t smem_u32(const void* p) {
    uint32_t a;
    asm("{ .reg .u64 t; cvta.to.shared.u64 t, %1; cvt.u32.u64 %0, t; }" : "=r"(a) : "l"(p));
    return a;
}

#define MBARRIER_INIT(mbar, cnt) \
    asm volatile("mbarrier.init.shared.b64 [%0], %1;" :: "r"((uint32_t)(mbar)), "r"((uint32_t)(cnt)) : "memory")

#define MBARRIER_EXPECT_TX(mbar, bytes) \
    asm volatile("mbarrier.arrive.expect_tx.shared.b64 _, [%0], %1;" :: "r"((uint32_t)(mbar)), "r"((uint32_t)(bytes)) : "memory")

#define MBARRIER_ARRIVE(mbar) \
    asm volatile("mbarrier.arrive.shared.b64 _, [%0];" :: "r"((uint32_t)(mbar)) : "memory")

#define MBARRIER_WAIT_PARITY(mbar, ph) do { \
    uint32_t _m = (uint32_t)(mbar); uint32_t _p = (uint32_t)(ph); uint32_t _d; \
    asm volatile("{\n\t.reg .pred p;\n\t" \
        "mbarrier.try_wait.parity.acquire.cta.shared::cta.b64 p, [%1], %2;\n\t" \
        "selp.b32 %0, 1, 0, p;\n\t}" : "=r"(_d) : "r"(_m), "r"(_p) : "memory"); \
    if (!_d) { \
        asm volatile("{\n\t.reg .pred P1;\n\t" \
            "WL_%=:\n\t" \
            "mbarrier.try_wait.parity.acquire.cta.shared::cta.b64 P1, [%0], %1, 0x989680;\n\t" \
            "@P1 bra.uni WD_%=;\n\t" \
            "bra.uni WL_%=;\n\t" \
            "WD_%=:\n\t}" :: "r"(_m), "r"(_p) : "memory"); \
    } \
} while (0)

#define TMA_LOAD_3D(smem, map, c0, c1, c2, mbar) \
    asm volatile("cp.async.bulk.tensor.3d.shared::cta.global.tile.mbarrier::complete_tx::bytes " \
                 "[%0], [%1, {%2, %3, %4}], [%5];" \
                 :: "r"((uint32_t)(smem)), "l"(map), "r"((int)(c0)), "r"((int)(c1)), "r"((int)(c2)), \
                    "r"((uint32_t)(mbar)) : "memory")

#define TMA_LOAD_5D(smem, map, c0, c1, c2, c3, c4, mbar) \
    asm volatile("cp.async.bulk.tensor.5d.shared::cta.global.tile.mbarrier::complete_tx::bytes " \
                 "[%0], [%1, {%2, %3, %4, %5, %6}], [%7];" \
                 :: "r"((uint32_t)(smem)), "l"(map), "r"((int)(c0)), "r"((int)(c1)), "r"((int)(c2)), \
                    "r"((int)(c3)), "r"((int)(c4)), "r"((uint32_t)(mbar)) : "memory")

__device__ __forceinline__ void ldsm4(uint32_t* r, uint32_t addr) {
    asm volatile("ldmatrix.sync.aligned.m8n8.x4.shared.b16 {%0,%1,%2,%3}, [%4];"
                 : "=r"(r[0]), "=r"(r[1]), "=r"(r[2]), "=r"(r[3]) : "r"(addr));
}

__device__ __forceinline__ void mma16816(float* d, const uint32_t* a, const uint32_t* b) {
    asm volatile("mma.sync.aligned.m16n8k16.row.col.f32.f16.f16.f32 "
                 "{%0,%1,%2,%3}, {%4,%5,%6,%7}, {%8,%9}, {%0,%1,%2,%3};"
                 : "+f"(d[0]), "+f"(d[1]), "+f"(d[2]), "+f"(d[3])
                 : "r"(a[0]), "r"(a[1]), "r"(a[2]), "r"(a[3]), "r"(b[0]), "r"(b[1]));
}

__device__ __forceinline__ float geluf(float v) {
    return 0.5f * v * (1.0f + erff(v * 0.70710678118654752f));
}

#define SWZ(off) ((off) ^ (((off) >> 3) & 0x70))

__device__ __forceinline__ void reduce2_part(float s, float q, float* dst) {
    __shared__ float rA[32], rB[32];
    const unsigned full = 0xffffffffu;
#pragma unroll
    for (int off = 16; off > 0; off >>= 1) {
        s += __shfl_down_sync(full, s, off);
        q += __shfl_down_sync(full, q, off);
    }
    int lane = threadIdx.x & 31, wid = threadIdx.x >> 5;
    int nw = (blockDim.x + 31) >> 5;
    if (lane == 0) { rA[wid] = s; rB[wid] = q; }
    __syncthreads();
    if (threadIdx.x == 0) {
        float S = 0.f, Q = 0.f;
        for (int w = 0; w < nw; w++) { S += rA[w]; Q += rB[w]; }
        dst[0] = S; dst[1] = Q;
    }
    __syncthreads();
}

__device__ __forceinline__ bool last_block(int idx, unsigned n) {
    __shared__ unsigned lb_done;
    __threadfence();
    if (threadIdx.x == 0) {
        unsigned old = atomicAdd(&g_cnt[idx], 1u);
        lb_done = (old == n - 1) ? 1u : 0u;
        if (lb_done) g_cnt[idx] = 0;
    }
    __syncthreads();
    if (lb_done) __threadfence();
    return lb_done != 0;
}

__device__ __forceinline__ void finalize_stats(const float* part, int n, double invN,
                                               float& mu, float& inv) {
    __shared__ float rA[32], rB[32], bc2[2];
    float s = 0.f, q = 0.f;
    for (int i = threadIdx.x; i < n; i += blockDim.x) {
        s += part[2 * i];
        q += part[2 * i + 1];
    }
    const unsigned full = 0xffffffffu;
#pragma unroll
    for (int off = 16; off > 0; off >>= 1) {
        s += __shfl_down_sync(full, s, off);
        q += __shfl_down_sync(full, q, off);
    }
    int lane = threadIdx.x & 31, wid = threadIdx.x >> 5;
    int nw = (blockDim.x + 31) >> 5;
    if (lane == 0) { rA[wid] = s; rB[wid] = q; }
    __syncthreads();
    if (threadIdx.x == 0) {
        float S = 0.f, Q = 0.f;
        for (int w = 0; w < nw; w++) { S += rA[w]; Q += rB[w]; }
        bc2[0] = S; bc2[1] = Q;
    }
    __syncthreads();
    double m = (double)bc2[0] * invN;
    double var = (double)bc2[1] * invN - m * m;
    mu = (float)m;
    inv = (float)(1.0 / sqrt(var + 1e-5));
}

// ---------------- grid gate (all blocks resident; self-resetting) ----------------
__device__ __forceinline__ bool gate_arrive(int gi, unsigned n) {
    __shared__ unsigned lastf;
    __threadfence();
    if (threadIdx.x == 0)
        lastf = (atomicAdd(&g_gA[gi], 1u) == n - 1) ? 1u : 0u;
    __syncthreads();
    return lastf != 0;
}
__device__ __forceinline__ void gate_release(int gi) {
    __threadfence();
    if (threadIdx.x == 0) atomicExch(&g_gR[gi], 1u);
}
__device__ __forceinline__ void gate_wait(int gi, unsigned n) {
    if (threadIdx.x == 0) {
        while (atomicAdd(&g_gR[gi], 0u) == 0u) __nanosleep(64);
    }
    __syncthreads();
    __threadfence();
    if (threadIdx.x == 0) {
        if (atomicAdd(&g_gB[gi], 1u) == n - 1) {
            g_gA[gi] = 0u;
            g_gB[gi] = 0u;
            atomicExch(&g_gR[gi], 0u);
        }
    }
}

// ---------------- kernel 1: stats of x + w2 transpose (+ reset conv2 job counter) ---
__global__ void __launch_bounds__(256) k_stats0wt2(const float* __restrict__ x,
                                                   const float* __restrict__ w2,
                                                   const float* __restrict__ w1,
                                                   const float* __restrict__ g0w,
                                                   const float* __restrict__ g0b) {
    int bid = blockIdx.x;
    int tid = threadIdx.x;
    if (bid == 0 && tid == 0) g_job = 0u;
    if (bid >= 512) {
        __shared__ float swt[2592];
        int base_oc = (bid - 512) * 32;
        const float* wsrc = w2 + base_oc * 81;
        for (int idx = tid; idx < 2592; idx += 256) swt[idx] = wsrc[idx];
        __syncthreads();
        for (int idx = tid; idx < 2592; idx += 256) {
            int t = idx >> 5;
            int ol = idx & 31;
            g_w2h[t * 16384 + base_oc + ol] = __float2half(swt[ol * 81 + t]);
        }
        return;
    }
    float s = 0.f, q = 0.f;
    int base = bid * 4096 + tid;
#pragma unroll
    for (int k = 0; k < 16; k++) {
        float v = x[base + k * 256];
        s += v;
        q = fmaf(v, v, q);
    }
    reduce2_part(s, q, &g_part0[bid * 2]);
    if (last_block(0, 512)) {
        float mu0, inv0;
        finalize_stats(g_part0, 512, 1.0 / (double)(CIN * SP), mu0, inv0);
        if (tid < 128) {
            int o = tid;
            float bias = 0.f;
            for (int c = 0; c < CIN; c++) {
                float a = inv0 * g0w[c];
                float b = g0b[c] - mu0 * a;
                float w = w1[o * CIN + c];
                g_w1eff[o * CIN + c] = w * a;
                bias = fmaf(w, b, bias);
            }
            g_bias1[o] = bias;
        }
    }
}

// ---------------- kernel 2: FUSED conv1 + GN1 + GELU + transpose ----------------
#define C1_W 32768
#define C1_AB 49152
#define C1_SMEM (C1_AB + 1024)

__global__ void __launch_bounds__(128) k_conv1g(const float* __restrict__ x,
                                                const float* __restrict__ gn1w,
                                                const float* __restrict__ gn1b) {
    extern __shared__ __align__(1024) char smem[];
    float* swf = (float*)(smem + C1_W);
    float* sab = (float*)(smem + C1_AB);
    __shared__ float sb[H];
    int tid = threadIdx.x;
    for (int i = tid; i < H * CIN; i += 128) swf[i] = g_w1eff[i];
    sb[tid] = g_bias1[tid];
    __syncthreads();
    int v = blockIdx.x * 128 + tid;
    float xr[CIN];
#pragma unroll
    for (int c = 0; c < CIN; c++) xr[c] = x[c * SP + v];
    float s = 0.f, q = 0.f;
    for (int o = 0; o < H; o++) {
        const float4* wr = (const float4*)(&swf[o * CIN]);
        float a0 = 0.f, a1 = 0.f, a2 = 0.f, a3 = 0.f;
#pragma unroll
        for (int g = 0; g < 2; g++) {
            float4 w0 = wr[g * 4 + 0], w1v = wr[g * 4 + 1], w2v = wr[g * 4 + 2], w3v = wr[g * 4 + 3];
            int b = g * 16;
            a0 = fmaf(w0.x, xr[b + 0], a0);  a0 = fmaf(w0.y, xr[b + 1], a0);
            a1 = fmaf(w0.z, xr[b + 2], a1);  a1 = fmaf(w0.w, xr[b + 3], a1);
            a0 = fmaf(w1v.x, xr[b + 4], a0); a0 = fmaf(w1v.y, xr[b + 5], a0);
            a1 = fmaf(w1v.z, xr[b + 6], a1); a1 = fmaf(w1v.w, xr[b + 7], a1);
            a2 = fmaf(w2v.x, xr[b + 8], a2); a2 = fmaf(w2v.y, xr[b + 9], a2);
            a3 = fmaf(w2v.z, xr[b + 10], a3); a3 = fmaf(w2v.w, xr[b + 11], a3);
            a2 = fmaf(w3v.x, xr[b + 12], a2); a2 = fmaf(w3v.y, xr[b + 13], a2);
            a3 = fmaf(w3v.z, xr[b + 14], a3); a3 = fmaf(w3v.w, xr[b + 15], a3);
        }
        float acc = sb[o] + (a0 + a1) + (a2 + a3);
        uint32_t off = (uint32_t)(tid * 256 + o * 2);
        *(__half*)(smem + SWZ(off)) = __float2half(acc);
        s += acc;
        q = fmaf(acc, acc, q);
    }
    reduce2_part(s, q, &g_part1[blockIdx.x * 2]);
    if (gate_arrive(0, 512)) {
        float mu1, inv1;
        finalize_stats(g_part1, 512, 1.0 / (double)(H * SP), mu1, inv1);
        float a = gn1w[tid] * inv1;
        g_a1[tid] = a;
        g_b1[tid] = gn1b[tid] - mu1 * a;
        gate_release(0);
    }
    gate_wait(0, 512);
    sab[tid] = g_a1[tid];
    sab[128 + tid] = g_b1[tid];
    __syncthreads();
    uint4* dst = (uint4*)&g_h1h[(size_t)v * 128];
#pragma unroll
    for (int k = 0; k < 16; k++) {
        uint4 hv = *(uint4*)(smem + SWZ((uint32_t)(tid * 256 + k * 16)));
        uint32_t w[4] = {hv.x, hv.y, hv.z, hv.w};
        uint32_t r[4];
#pragma unroll
        for (int p = 0; p < 4; p++) {
            int c0 = k * 8 + p * 2;
            __half2 h2v = *(__half2*)&w[p];
            float f0 = geluf(fmaf(sab[c0], __half2float(h2v.x), sab[128 + c0]));
            float f1 = geluf(fmaf(sab[c0 + 1], __half2float(h2v.y), sab[128 + c0 + 1]));
            __half2 o2 = __floats2half2_rn(f0, f1);
            r[p] = *(uint32_t*)&o2;
        }
        dst[k] = make_uint4(r[0], r[1], r[2], r[3]);
    }
}

// ---------------- kernel 3: conv2 PERSISTENT (148 CTAs, work-stealing; r16) --------
#define NSTAGE 2
#define STAGE_BYTES 98304
#define SM_DATA 1024
#define SMEM_TOTAL (SM_DATA + NSTAGE * STAGE_BYTES)
#define TILE_TX 98304
#define NJOBS 256

__device__ __forceinline__ void issue_tile2(uint32_t sb, int st, int i, int xx, int yy,
                                            const CUtensorMap* tw, const CUtensorMap* tx) {
    uint32_t fullb = sb + st * 8;
    MBARRIER_EXPECT_TX(fullb, TILE_TX);
    int dx = i / 27;
    int r27 = i - dx * 27;
    int dy = r27 / 9;
    int r9 = r27 - dy * 9;
    int dz = r9 / 3;
    int dw = r9 - dz * 3;
    uint32_t D = sb + SM_DATA + st * STAGE_BYTES;
    TMA_LOAD_3D(D, tw, 0, 0, i, fullb);
    TMA_LOAD_3D(D + 16384, tw, 64, 0, i, fullb);
    TMA_LOAD_5D(D + 32768, tx, 0, dw - 1, dz - 1, yy + dy - 1, xx + dx - 1, fullb);
    TMA_LOAD_5D(D + 65536, tx, 64, dw - 1, dz - 1, yy + dy - 1, xx + dx - 1, fullb);
}

__global__ void __launch_bounds__(512, 1) k_conv2mma(const __grid_constant__ CUtensorMap tw,
                                                     const __grid_constant__ CUtensorMap tx,
                                                     const float* __restrict__ gn2w,
                                                     const float* __restrict__ gn2b) {
    extern __shared__ __align__(1024) char smem[];
    uint32_t sb = smem_u32(smem);
    __shared__ int sjob;
    int tid = threadIdx.x;
    int lane = tid & 31, wid = tid >> 5;
    int wm = wid & 3, wn = wid >> 2;

    if (tid == 0) {
        for (int s = 0; s < NSTAGE; s++) {
            MBARRIER_INIT(sb + s * 8, 1);
            MBARRIER_INIT(sb + 32 + s * 8, 16);
        }
    }
    __syncthreads();

    const uint32_t swx = (lane & 7) << 4;
    const uint32_t aSel = lane >> 4;
    const uint32_t bSel = (lane >> 3) & 1;
    const int aRow = wm * 32 + (lane & 15);
    const int bRow = wn * 64 + (lane & 7) + ((lane >> 4) << 3);

    unsigned gt = 0;
    unsigned ct = 0;
    int eph0 = 0, eph1 = 0;
    int cph0 = 0, cph1 = 0;

    for (;;) {
        if (tid == 0) sjob = (int)atomicAdd(&g_job, 1u);
        __syncthreads();
        int job = sjob;
        if (job >= NJOBS) break;
        int xx = job >> 4, yy = job & 15;

        if (tid == 0) {
#pragma unroll
            for (int t = 0; t < 2; t++) {
                int st = (int)(gt & 1u);
                if (gt >= 2) {
                    if (st == 0) { MBARRIER_WAIT_PARITY(sb + 32, eph0); eph0 ^= 1; }
                    else         { MBARRIER_WAIT_PARITY(sb + 40, eph1); eph1 ^= 1; }
                }
                issue_tile2(sb, st, t, xx, yy, &tw, &tx);
                gt++;
            }
        }

        float acc[2][8][4];
#pragma unroll
        for (int a = 0; a < 2; a++)
#pragma unroll
            for (int b = 0; b < 8; b++)
#pragma unroll
                for (int cc = 0; cc < 4; cc++) acc[a][b][cc] = 0.f;

        for (int i = 0; i < 81; i++) {
            int st = (int)(ct & 1u);
            if (st == 0) { MBARRIER_WAIT_PARITY(sb + 0, cph0); cph0 ^= 1; }
            else         { MBARRIER_WAIT_PARITY(sb + 8, cph1); cph1 ^= 1; }
            ct++;
            uint32_t D = sb + SM_DATA + st * STAGE_BYTES;
#pragma unroll
            for (int j = 0; j < 8; j++) {
                int half = j >> 2, jl = j & 3;
                uint32_t aB0 = D + half * 16384 + aRow * 128;
                uint32_t bB0 = D + 32768 + half * 32768 + bRow * 128;
                uint32_t ac = (((2 * jl + aSel) << 4) ^ swx);
                uint32_t bc = (((2 * jl + bSel) << 4) ^ swx);
                uint32_t a0[4], a1[4], bb[8];
                ldsm4(a0, aB0 + ac);
                ldsm4(a1, aB0 + 2048 + ac);
                ldsm4(bb + 0, bB0 + bc);
                ldsm4(bb + 4, bB0 + 2048 + bc);
#pragma unroll
                for (int n8 = 0; n8 < 4; n8++) {
                    const uint32_t* bp = &bb[(n8 >> 1) * 4 + (n8 & 1) * 2];
                    mma16816(acc[0][n8], a0, bp);
                    mma16816(acc[1][n8], a1, bp);
                }
                ldsm4(bb + 0, bB0 + 4096 + bc);
                ldsm4(bb + 4, bB0 + 6144 + bc);
#pragma unroll
                for (int n8 = 4; n8 < 8; n8++) {
                    const uint32_t* bp = &bb[((n8 - 4) >> 1) * 4 + (n8 & 1) * 2];
                    mma16816(acc[0][n8], a0, bp);
                    mma16816(acc[1][n8], a1, bp);
                }
            }
            if (lane == 0) MBARRIER_ARRIVE(sb + 32 + st * 8);
            if (tid == 0 && i + 2 < 81) {
                int st2 = (int)(gt & 1u);
                if (st2 == 0) { MBARRIER_WAIT_PARITY(sb + 32, eph0); eph0 ^= 1; }
                else          { MBARRIER_WAIT_PARITY(sb + 40, eph1); eph1 ^= 1; }
                issue_tile2(sb, st2, i + 2, xx, yy, &tw, &tx);
                gt++;
            }
        }

        int g2 = lane >> 2, tc = lane & 3;
        int vb = job * 256;
        float s = 0.f, q = 0.f;
#pragma unroll
        for (int mt = 0; mt < 2; mt++) {
#pragma unroll
            for (int n8 = 0; n8 < 8; n8++) {
                float* d = acc[mt][n8];
                int o = wm * 32 + mt * 16 + g2;
                int v = vb + wn * 64 + n8 * 8 + tc * 2;
                *(__half2*)&g_h2[o * SP + v] = __floats2half2_rn(d[0], d[1]);
                *(__half2*)&g_h2[(o + 8) * SP + v] = __floats2half2_rn(d[2], d[3]);
                s += d[0] + d[1] + d[2] + d[3];
                q = fmaf(d[0], d[0], q);
                q = fmaf(d[1], d[1], q);
                q = fmaf(d[2], d[2], q);
                q = fmaf(d[3], d[3], q);
            }
        }
        reduce2_part(s, q, &g_part2[job * 2]);
        if (last_block(2, NJOBS)) {
            float mu2, inv2;
            finalize_stats(g_part2, NJOBS, 1.0 / (double)(H * SP), mu2, inv2);
            if (tid < 128) {
                float a = gn2w[tid] * inv2;
                g_a2[tid] = a;
                g_b2[tid] = gn2b[tid] - mu2 * a;
            }
        }
    }
}

// ---------------- kernel 4: GN2+GELU + transpose h2 -> g_h1h; SE in last ------------
// Phase 1 rewritten: uint4 global loads (8 v per load), per-(c,vgroup) register sums.
__global__ void __launch_bounds__(256) k_gelu2t(const float* __restrict__ sew1,
                                                const float* __restrict__ sew2,
                                                const float* __restrict__ w3) {
    __shared__ __align__(16) __half sm[128 * 132];
    __shared__ float sa[128], sbf[128];
    __shared__ float psum[128 * 16];       // [c][vgroup] partial sums
    int v0 = blockIdx.x * 128;
    int tid = threadIdx.x;
    if (tid < 128) { sa[tid] = g_a2[tid]; sbf[tid] = g_b2[tid]; }
    __syncthreads();
    // phase 1: thread owns vgroup vg (8 voxels) x 8 channels (cq, cq+16, ...)
    int vg = tid & 15;          // 0..15 -> voxels vg*8 .. vg*8+7
    int cq = tid >> 4;          // 0..15 -> channels cq + 16k
#pragma unroll
    for (int k = 0; k < 8; k++) {
        int c = cq + 16 * k;
        float a = sa[c], b = sbf[c];
        uint4 hv = *(const uint4*)&g_h2[c * SP + v0 + vg * 8];
        uint32_t w[4] = {hv.x, hv.y, hv.z, hv.w};
        float csum = 0.f;
#pragma unroll
        for (int p = 0; p < 4; p++) {
            __half2 h2v = *(__half2*)&w[p];
            float f0 = geluf(fmaf(a, __half2float(h2v.x), b));
            float f1 = geluf(fmaf(a, __half2float(h2v.y), b));
            int vv = vg * 8 + p * 2;
            sm[vv * 132 + c] = __float2half(f0);
            sm[(vv + 1) * 132 + c] = __float2half(f1);
            csum += f0 + f1;
        }
        psum[c * 16 + vg] = csum;
    }
    __syncthreads();
    // phase 2: transposed write to g_h1h [v][c]
    uint2* dst = (uint2*)&g_h1h[(size_t)v0 * 128];
    for (int idx = tid; idx < 4096; idx += 256) {
        int row = idx >> 5, part = idx & 31;
        const uint2* src = (const uint2*)&sm[row * 132 + part * 4];
        dst[idx] = *src;
    }
    // phase 3: chsum from psum
    if (tid < 128) {
        const float* p = &psum[tid * 16];
        float s = 0.f;
#pragma unroll
        for (int k = 0; k < 16; k++) s += p[k];
        g_chsump[blockIdx.x * 128 + tid] = s;
    }
    if (last_block(3, 512)) {
        __shared__ float m[H];
        __shared__ float t1[SED];
        if (tid < 128) {
            float cssum = 0.f;
            for (int k = 0; k < 512; k++) cssum += g_chsump[k * 128 + tid];
            m[tid] = cssum * (1.f / 65536.f);
        }
        __syncthreads();
        if (tid < SED) {
            float acc = 0.f;
            for (int j = 0; j < H; j++) acc = fmaf(sew1[tid * H + j], m[j], acc);
            t1[tid] = geluf(acc);
        }
        __syncthreads();
        if (tid < 128) {
            float acc = 0.f;
#pragma unroll
            for (int j = 0; j < SED; j++) acc = fmaf(sew2[tid * SED + j], t1[j], acc);
            float sg = 1.f / (1.f + expf(-acc));
            for (int o = 0; o < COUT; o++)
                g_w3h[o * H + tid] = __float2half(w3[o * H + tid] * sg);
        }
    }
}

// ---------------- kernel 5: conv3 mma + GN3 (single gate) -> out --------------------
#define SM3_A 1024
#define SM3_B 9216
#define SMEM3_TOTAL (SM3_B + 65536)

__global__ void __launch_bounds__(256) k_conv3f(const __grid_constant__ CUtensorMap tx,
                                                const float* __restrict__ gn3w,
                                                const float* __restrict__ gn3b,
                                                float* __restrict__ out) {
    extern __shared__ __align__(1024) char smem[];
    uint32_t sb = smem_u32(smem);
    __shared__ float sab3[2 * COUT];
    int tid = threadIdx.x;
    int lane = tid & 31, wid = tid >> 5;
    int wm = wid & 1, wn = wid >> 1;
    int bx = blockIdx.x;
    int xx = bx >> 4, yy = bx & 15;

    if (tid == 0) MBARRIER_INIT(sb, 1);
    __syncthreads();
    if (tid == 0) {
        MBARRIER_EXPECT_TX(sb, 65536);
        TMA_LOAD_5D(sb + SM3_B, &tx, 0, 0, 0, yy, xx, sb);
        TMA_LOAD_5D(sb + SM3_B + 32768, &tx, 64, 0, 0, yy, xx, sb);
    }
    for (int idx = tid; idx < 4096; idx += 256) {
        int o = idx >> 7;
        int c = idx & 127;
        uint32_t off = (uint32_t)(o * 128 + (c & 63) * 2);
        *(__half*)(smem + SM3_A + (c >> 6) * 4096 + SWZ(off)) = g_w3h[idx];
    }
    __syncthreads();
    MBARRIER_WAIT_PARITY(sb, 0);

    float acc[8][4];
#pragma unroll
    for (int b = 0; b < 8; b++)
#pragma unroll
        for (int cc = 0; cc < 4; cc++) acc[b][cc] = 0.f;

    const uint32_t swx = (lane & 7) << 4;
    const uint32_t aSel = lane >> 4;
    const uint32_t bSel = (lane >> 3) & 1;
    const int aRow = wm * 16 + (lane & 15);
    const int bRow = wn * 64 + (lane & 7) + ((lane >> 4) << 3);

#pragma unroll
    for (int h = 0; h < 2; h++) {
        uint32_t aB = sb + SM3_A + h * 4096 + aRow * 128;
        uint32_t bB = sb + SM3_B + h * 32768 + bRow * 128;
#pragma unroll
        for (int j = 0; j < 4; j++) {
            uint32_t ac = (((2 * j + aSel) << 4) ^ swx);
            uint32_t bc = (((2 * j + bSel) << 4) ^ swx);
            uint32_t a0[4], bb[8];
            ldsm4(a0, aB + ac);
            ldsm4(bb + 0, bB + bc);
            ldsm4(bb + 4, bB + 2048 + bc);
#pragma unroll
            for (int n8 = 0; n8 < 4; n8++) {
                const uint32_t* bp = &bb[(n8 >> 1) * 4 + (n8 & 1) * 2];
                mma16816(acc[n8], a0, bp);
            }
            ldsm4(bb + 0, bB + 4096 + bc);
            ldsm4(bb + 4, bB + 6144 + bc);
#pragma unroll
            for (int n8 = 4; n8 < 8; n8++) {
                const uint32_t* bp = &bb[((n8 - 4) >> 1) * 4 + (n8 & 1) * 2];
                mma16816(acc[n8], a0, bp);
            }
        }
    }

    float s = 0.f, q = 0.f;
#pragma unroll
    for (int n8 = 0; n8 < 8; n8++) {
        float* d = acc[n8];
        s += d[0] + d[1] + d[2] + d[3];
        q = fmaf(d[0], d[0], q);
        q = fmaf(d[1], d[1], q);
        q = fmaf(d[2], d[2], q);
        q = fmaf(d[3], d[3], q);
    }
    reduce2_part(s, q, &g_part3[bx * 2]);
    if (gate_arrive(2, 256)) {
        float mu3, inv3;
        finalize_stats(g_part3, 256, 1.0 / (double)(COUT * SP), mu3, inv3);
        if (tid < COUT) {
            float a = gn3w[tid] * inv3;
            g_a3[tid] = a;
            g_b3[tid] = gn3b[tid] - mu3 * a;
        }
        gate_release(2);
    }
    gate_wait(2, 256);
    if (tid < COUT) { sab3[tid] = g_a3[tid]; sab3[COUT + tid] = g_b3[tid]; }
    __syncthreads();

    int g2 = lane >> 2, tc = lane & 3;
    int vb = bx * 256;
#pragma unroll
    for (int n8 = 0; n8 < 8; n8++) {
        float* d = acc[n8];
        int o = wm * 16 + g2;
        int v = vb + wn * 64 + n8 * 8 + tc * 2;
        float a0 = sab3[o], b0 = sab3[COUT + o];
        float a8 = sab3[o + 8], b8 = sab3[COUT + o + 8];
        *(float2*)&out[o * SP + v] = make_float2(fmaf(a0, d[0], b0), fmaf(a0, d[1], b0));
        *(float2*)&out[(o + 8) * SP + v] = make_float2(fmaf(a8, d[2], b8), fmaf(a8, d[3], b8));
    }
}

// ---------------- launcher ----------------
typedef CUresult (CUDAAPI* PFN_tmapEncode)(
    CUtensorMap*, CUtensorMapDataType, cuuint32_t, void*,
    const cuuint64_t*, const cuuint64_t*, const cuuint32_t*, const cuuint32_t*,
    CUtensorMapInterleave, CUtensorMapSwizzle, CUtensorMapL2promotion, CUtensorMapFloatOOBfill);

extern "C" void kernel_launch(void* const* d_in, const int* in_sizes, int n_in,
                              void* d_out, int out_size) {
    const float* x    = (const float*)d_in[0];
    const float* g0w  = (const float*)d_in[1];
    const float* g0b  = (const float*)d_in[2];
    const float* w1   = (const float*)d_in[3];
    const float* gn1w = (const float*)d_in[4];
    const float* gn1b = (const float*)d_in[5];
    const float* w2   = (const float*)d_in[6];
    const float* gn2w = (const float*)d_in[7];
    const float* gn2b = (const float*)d_in[8];
    const float* sew1 = (const float*)d_in[9];
    const float* sew2 = (const float*)d_in[10];
    const float* w3   = (const float*)d_in[11];
    const float* gn3w = (const float*)d_in[12];
    const float* gn3b = (const float*)d_in[13];
    float* out = (float*)d_out;

    PFN_tmapEncode encode = nullptr;
    {
        void* fp = nullptr;
        cudaDriverEntryPointQueryResult qr;
        cudaGetDriverEntryPoint("cuTensorMapEncodeTiled", &fp, cudaEnableDefault, &qr);
        encode = (PFN_tmapEncode)fp;
    }

    void* pw = nullptr; void* px = nullptr;
    cudaGetSymbolAddress(&pw, g_w2h);
    cudaGetSymbolAddress(&px, g_h1h);
    CUtensorMap tw, tx;
    {
        cuuint64_t dims[3] = {128, 128, 81};
        cuuint64_t strides[2] = {256, 32768};
        cuuint32_t box[3] = {64, 128, 1};
        cuuint32_t es[3] = {1, 1, 1};
        encode(&tw, CU_TENSOR_MAP_DATA_TYPE_FLOAT16, 3, pw, dims, strides, box, es,
               CU_TENSOR_MAP_INTERLEAVE_NONE, CU_TENSOR_MAP_SWIZZLE_128B,
               CU_TENSOR_MAP_L2_PROMOTION_L2_128B, CU_TENSOR_MAP_FLOAT_OOB_FILL_NONE);
    }
    {
        cuuint64_t dims[5] = {128, 16, 16, 16, 16};
        cuuint64_t strides[4] = {256, 4096, 65536, 1048576};
        cuuint32_t box[5] = {64, 16, 16, 1, 1};
        cuuint32_t es[5] = {1, 1, 1, 1, 1};
        encode(&tx, CU_TENSOR_MAP_DATA_TYPE_FLOAT16, 5, px, dims, strides, box, es,
               CU_TENSOR_MAP_INTERLEAVE_NONE, CU_TENSOR_MAP_SWIZZLE_128B,
               CU_TENSOR_MAP_L2_PROMOTION_L2_128B, CU_TENSOR_MAP_FLOAT_OOB_FILL_NONE);
    }
    cudaFuncSetAttribute(k_conv1g, cudaFuncAttributeMaxDynamicSharedMemorySize, C1_SMEM);
    cudaFuncSetAttribute(k_conv2mma, cudaFuncAttributeMaxDynamicSharedMemorySize, SMEM_TOTAL);
    cudaFuncSetAttribute(k_conv3f, cudaFuncAttributeMaxDynamicSharedMemorySize, SMEM3_TOTAL);

    k_stats0wt2<<<1024, 256>>>(x, w2, w1, g0w, g0b);
    k_conv1g<<<512, 128, C1_SMEM>>>(x, gn1w, gn1b);
    k_conv2mma<<<148, 512, SMEM_TOTAL>>>(tw, tx, gn2w, gn2b);   // persistent
    k_gelu2t<<<512, 256>>>(sew1, sew2, w3);
    k_conv3f<<<256, 256, SMEM3_TOTAL>>>(tx, gn3w, gn3b, out);
}